// round 8
// baseline (speedup 1.0000x reference)
#include <cuda_runtime.h>
#include <math.h>
#include <stdint.h>

#define B_  4
#define L_  2048
#define D_  768
#define H_  12
#define HD_ 64
#define M_  (B_*L_)

// ---------------------------------------------------------------------------
// Scratch (device globals; all values tf32-rounded fp32)
// ---------------------------------------------------------------------------
__device__ float g_xt[(size_t)M_*D_];    // x rounded
__device__ float g_q [(size_t)M_*D_];    // [B,H,L,hd], pre-scaled 1/8
__device__ float g_k [(size_t)M_*D_];    // [B,H,L,hd]
__device__ float g_vt[(size_t)M_*D_];    // [B,H,hd,L]  (transposed!)
__device__ float g_o [(size_t)M_*D_];    // [M,D] attention output
__device__ float g_wt[4][(size_t)D_*D_]; // W^T rounded (q,k,v,o)

// ---------------------------------------------------------------------------
// Baseline-PTX helpers (sm_80-era: valid at target sm_103)
// ---------------------------------------------------------------------------
__device__ __forceinline__ uint32_t smem_to_u32(const void* p) {
    uint32_t a;
    asm("{ .reg .u64 t; cvta.to.shared.u64 t, %1; cvt.u32.u64 %0, t; }"
        : "=r"(a) : "l"(p));
    return a;
}
__device__ __forceinline__ void ldsm_x4(uint32_t addr, uint32_t* r) {
    asm volatile("ldmatrix.sync.aligned.m8n8.x4.shared.b16 {%0,%1,%2,%3}, [%4];"
                 : "=r"(r[0]), "=r"(r[1]), "=r"(r[2]), "=r"(r[3]) : "r"(addr));
}
__device__ __forceinline__ void mma_tf32(float* c, const uint32_t* a,
                                         const uint32_t b0, const uint32_t b1) {
    asm volatile("mma.sync.aligned.m16n8k8.row.col.f32.tf32.tf32.f32 "
                 "{%0,%1,%2,%3}, {%4,%5,%6,%7}, {%8,%9}, {%0,%1,%2,%3};"
                 : "+f"(c[0]), "+f"(c[1]), "+f"(c[2]), "+f"(c[3])
                 : "r"(a[0]), "r"(a[1]), "r"(a[2]), "r"(a[3]), "r"(b0), "r"(b1));
}
__device__ __forceinline__ float rna(float x) {
    uint32_t u;
    asm("cvt.rna.tf32.f32 %0, %1;" : "=r"(u) : "f"(x));
    return __uint_as_float(u);
}
__device__ __forceinline__ float trunc_tf32(float x) {
    return __uint_as_float(__float_as_uint(x) & 0xFFFFE000u);
}
#define CP_ASYNC16(saddr, gptr) \
    asm volatile("cp.async.cg.shared.global [%0], [%1], 16;" \
                 :: "r"(saddr), "l"(gptr))
#define CP_COMMIT()  asm volatile("cp.async.commit_group;" ::: "memory")
#define CP_WAIT(N)   asm volatile("cp.async.wait_group %0;" :: "n"(N) : "memory")

// 128B-row swizzle: 16B-chunk bits XOR row bits [0:3)
#define SW128R(row, cb) ((uint32_t)((row) * 128 + ((cb) ^ (((row) & 7) << 4))))
// 256B-row swizzle (attention tiles keep 256B rows)
#define SW256(row, cb)  ((uint32_t)((row) * 256 + ((cb) ^ (((row) & 7) << 4))))

// ---------------------------------------------------------------------------
// Fused preprocessing: blocks [0,6144) round x; blocks [6144,8448) transpose+
// round one 32x32 tile of one of the 4 weight matrices.
// ---------------------------------------------------------------------------
#define RX_BLOCKS 6144
#define TP_BLOCKS_PER_W 576

__global__ __launch_bounds__(256)
void preprocess(const float* __restrict__ x, float* __restrict__ xt,
                const float* __restrict__ W0, const float* __restrict__ W1,
                const float* __restrict__ W2, const float* __restrict__ W3,
                float* __restrict__ wt)
{
    const int bid = blockIdx.x;
    const int tid = threadIdx.x;
    if (bid < RX_BLOCKS) {
        size_t i = ((size_t)bid * 256 + tid) * 4;
        float4 v = *(const float4*)(x + i);
        v.x = rna(v.x); v.y = rna(v.y); v.z = rna(v.z); v.w = rna(v.w);
        *(float4*)(xt + i) = v;
        return;
    }
    __shared__ float t[32][33];
    const int tt = bid - RX_BLOCKS;
    const int w  = tt / TP_BLOCKS_PER_W;
    const int tile = tt % TP_BLOCKS_PER_W;
    const int bx = tile % (D_ / 32), by = tile / (D_ / 32);
    const float* W = (w == 0) ? W0 : (w == 1) ? W1 : (w == 2) ? W2 : W3;
    float* WT = wt + (size_t)w * D_ * D_;
    const int tx = tid & 31, ty = tid >> 5;   // 32 x 8
    const int x0 = bx * 32, y0 = by * 32;
#pragma unroll
    for (int i = 0; i < 32; i += 8)
        t[ty + i][tx] = W[(size_t)(y0 + ty + i) * D_ + x0 + tx];
    __syncthreads();
#pragma unroll
    for (int i = 0; i < 32; i += 8)
        WT[(size_t)(x0 + ty + i) * D_ + y0 + tx] = rna(t[tx][ty + i]);
}

// ---------------------------------------------------------------------------
// tf32 GEMM via mma.sync.m16n8k8: C[M,N] = A @ Bt^T + bias.
// 128x128 CTA tile, 8 warps (2m x 4n); K-chunks of 32 floats (128B rows),
// 3-stage cp.async (32KB/stage, 96KB total) -> 2 CTAs/SM.
// OUT_MODE: 0 = fp32 [M,D]; 1 = head-split [B,H,L,hd] (rna, scaled);
//           2 = head-split transposed [B,H,hd,L] (rna) for V.
// ---------------------------------------------------------------------------
#define G_SSZ   32768
#define G_OFF_B 16384
#define G_DYN   (3 * G_SSZ + 1024)

template<int OUT_MODE>
__global__ __launch_bounds__(256, 2)
void mm_gemm(const float* __restrict__ A, const float* __restrict__ Bt,
             const float* __restrict__ bias, float scale, float* __restrict__ C)
{
    extern __shared__ char dsm[];
    const uint32_t raw  = smem_to_u32(dsm);
    const uint32_t base = (raw + 1023) & ~1023u;

    const int tid  = threadIdx.x;
    const int wid  = tid >> 5;
    const int lane = tid & 31;
    const int wm   = wid & 1;
    const int wn   = wid >> 1;
    const int m0 = blockIdx.y * 128;
    const int n0 = blockIdx.x * 128;

    // loader: thread -> row tid>>1, half-row (tid&1)*64B, 4 chunks of 16B
    const int lrow = tid >> 1;
    const int lcb0 = (tid & 1) * 64;
    const float* gA = A  + (size_t)(m0 + lrow) * D_ + (lcb0 >> 2);
    const float* gB = Bt + (size_t)(n0 + lrow) * D_ + (lcb0 >> 2);

    auto load_chunk = [&](int kc, int stg) {
        const uint32_t sb = base + (uint32_t)stg * G_SSZ;
        const int kf = kc * 32;
#pragma unroll
        for (int c = 0; c < 4; c++) {
            const uint32_t so = SW128R(lrow, lcb0 + c * 16);
            CP_ASYNC16(sb + so,           gA + kf + c * 4);
            CP_ASYNC16(sb + G_OFF_B + so, gB + kf + c * 4);
        }
    };

    const int arow = wm * 64 + (lane & 7) + ((lane >> 3) & 1) * 8;
    const int acb  = (lane >> 4) * 16;
    const int brow = wn * 32 + (lane & 7) + ((lane >> 4) & 1) * 8;
    const int bcb  = ((lane >> 3) & 1) * 16;

    float acc[4][4][4];
#pragma unroll
    for (int mi = 0; mi < 4; mi++)
#pragma unroll
        for (int nt = 0; nt < 4; nt++)
#pragma unroll
            for (int c = 0; c < 4; c++) acc[mi][nt][c] = 0.0f;

    const int NCH = D_ / 32;   // 24
    load_chunk(0, 0); CP_COMMIT();
    load_chunk(1, 1); CP_COMMIT();

    int sload = 2, scomp = 0;
    for (int i = 0; i < NCH; i++) {
        if (i == NCH - 1) { CP_WAIT(0); } else { CP_WAIT(1); }
        __syncthreads();
        if (i + 2 < NCH) {
            load_chunk(i + 2, sload);
            CP_COMMIT();
            if (++sload == 3) sload = 0;
        }
        const uint32_t sb = base + (uint32_t)scomp * G_SSZ;
        if (++scomp == 3) scomp = 0;
#pragma unroll
        for (int ks = 0; ks < 4; ks++) {
            uint32_t a[4][4], bf[2][4];
#pragma unroll
            for (int mi = 0; mi < 4; mi++)
                ldsm_x4(sb + SW128R(arow + mi * 16, acb + ks * 32), a[mi]);
#pragma unroll
            for (int nbh = 0; nbh < 2; nbh++)
                ldsm_x4(sb + G_OFF_B + SW128R(brow + nbh * 16, bcb + ks * 32), bf[nbh]);
#pragma unroll
            for (int mi = 0; mi < 4; mi++)
#pragma unroll
                for (int nt = 0; nt < 4; nt++)
                    mma_tf32(acc[mi][nt], a[mi],
                             bf[nt >> 1][(nt & 1) * 2], bf[nt >> 1][(nt & 1) * 2 + 1]);
        }
    }

    // epilogue
    const int grp = lane >> 2;
    const int tig = lane & 3;
#pragma unroll
    for (int nt = 0; nt < 4; nt++) {
        const int col = n0 + wn * 32 + nt * 8 + tig * 2;
        const float b0 = bias[col], b1 = bias[col + 1];
#pragma unroll
        for (int mi = 0; mi < 4; mi++)
#pragma unroll
            for (int half = 0; half < 2; half++) {
                const int m = m0 + wm * 64 + mi * 16 + grp + half * 8;
                const float v0 = (acc[mi][nt][half * 2 + 0] + b0) * scale;
                const float v1 = (acc[mi][nt][half * 2 + 1] + b1) * scale;
                if (OUT_MODE == 0) {
                    float2 v; v.x = v0; v.y = v1;
                    *(float2*)(C + (size_t)m * D_ + col) = v;
                } else if (OUT_MODE == 1) {
                    const int batch = m / L_, lr = m % L_;
                    const int h = col / HD_, d0 = col % HD_;
                    float2 v; v.x = rna(v0); v.y = rna(v1);
                    *(float2*)(C + (((size_t)(batch * H_ + h) * L_ + lr) * HD_ + d0)) = v;
                } else {   // V transposed: [B,H,hd,L]
                    const int batch = m / L_, lr = m % L_;
                    const int h = col / HD_, d0 = col % HD_;
                    const size_t vb = ((size_t)(batch * H_ + h) * HD_ + d0) * L_ + lr;
                    C[vb]      = rna(v0);
                    C[vb + L_] = rna(v1);
                }
            }
    }
}

// ---------------------------------------------------------------------------
// tf32 flash attention via mma.sync.m16n8k8. 256 threads / 8 warps;
// warp = 16 q-rows x 64 kv tile. Q fragments register-resident; K + V^T in
// 3-stage cp.async ring (32KB/stage). P round-trips through a warp-private
// smem tile (truncated to tf32 bits; l summed from the same truncated
// values so normalization cancels truncation bias). No online-max.
// ---------------------------------------------------------------------------
#define AT_P    32768
#define AT_STG  65536
#define AT_SSZ  32768
#define AT_VOFF 16384
#define AT_DYN  (AT_STG + 3 * AT_SSZ + 1024)

__global__ __launch_bounds__(256)
void attn_tf32(const float* __restrict__ Q, const float* __restrict__ K,
               const float* __restrict__ VT, float* __restrict__ O)
{
    extern __shared__ char dsm[];
    const uint32_t raw  = smem_to_u32(dsm);
    const uint32_t base = (raw + 1023) & ~1023u;
    char* smp = dsm + (base - raw);

    const int tid = threadIdx.x;
    const int wid = tid >> 5;
    const int lane = tid & 31;
    const int b = blockIdx.z, h = blockIdx.y;
    const int q0 = blockIdx.x * 128;
    const size_t hoff = (size_t)(b * H_ + h) * L_ * HD_;

    // Q load: 128 rows x 256B
    {
        const int r = tid >> 1, cb0 = (tid & 1) * 128;
        const float* g = Q + hoff + (size_t)(q0 + r) * HD_ + (cb0 >> 2);
#pragma unroll
        for (int c = 0; c < 8; c++)
            CP_ASYNC16(base + SW256(r, cb0 + c * 16), g + c * 4);
    }
    const int sr = tid >> 2, scb0 = (tid & 3) * 64;
    auto load_stage = [&](int kt, int stg) {
        const uint32_t sb = base + AT_STG + (uint32_t)stg * AT_SSZ;
        const float* gk = K  + hoff + (size_t)(kt + sr) * HD_ + (scb0 >> 2);
        const float* gv = VT + hoff + (size_t)sr * L_ + kt + (scb0 >> 2);
#pragma unroll
        for (int c = 0; c < 4; c++) {
            const uint32_t so = SW256(sr, scb0 + c * 16);
            CP_ASYNC16(sb + so,           gk + c * 4);
            CP_ASYNC16(sb + AT_VOFF + so, gv + c * 4);
        }
    };
    load_stage(0, 0);  CP_COMMIT();   // g0: Q + stage0
    load_stage(64, 1); CP_COMMIT();   // g1: stage1
    CP_WAIT(1);
    __syncthreads();

    const int ar = (lane & 7) + ((lane >> 3) & 1) * 8;
    const int ac = (lane >> 4) * 16;
    const int br = (lane & 7) + ((lane >> 4) & 1) * 8;
    const int bc = ((lane >> 3) & 1) * 16;

    // Q fragments (register-resident)
    uint32_t qf[8][4];
#pragma unroll
    for (int ks = 0; ks < 8; ks++)
        ldsm_x4(base + SW256(wid * 16 + ar, ks * 32 + ac), qf[ks]);

    float oacc[8][4];
#pragma unroll
    for (int nt = 0; nt < 8; nt++)
#pragma unroll
        for (int c = 0; c < 4; c++) oacc[nt][c] = 0.0f;
    float l0 = 0.0f, l1 = 0.0f;

    const uint32_t pbase = base + AT_P + (uint32_t)wid * 4096;
    char* psmp = smp + AT_P + wid * 4096;
    const int prow = lane >> 2;
    const int pcb  = (lane & 3) * 8;

    const int NIT = L_ / 64;   // 32
    int sload = 2, scomp = 0;
    for (int it = 0; it < NIT; it++) {
        if (it > 0) {
            if (it == NIT - 1) { CP_WAIT(0); } else { CP_WAIT(1); }
            __syncthreads();
        }
        if (it + 2 < NIT) {
            load_stage((it + 2) * 64, sload);
            CP_COMMIT();
            if (++sload == 3) sload = 0;
        }
        const uint32_t sb = base + AT_STG + (uint32_t)scomp * AT_SSZ;
        if (++scomp == 3) scomp = 0;

        // ---- S = Q K^T ----
        float sacc[8][4];
#pragma unroll
        for (int nt = 0; nt < 8; nt++)
#pragma unroll
            for (int c = 0; c < 4; c++) sacc[nt][c] = 0.0f;
#pragma unroll
        for (int ks = 0; ks < 8; ks++) {
            uint32_t kf[4][4];
#pragma unroll
            for (int nbh = 0; nbh < 4; nbh++)
                ldsm_x4(sb + SW256(nbh * 16 + br, ks * 32 + bc), kf[nbh]);
#pragma unroll
            for (int nt = 0; nt < 8; nt++)
                mma_tf32(sacc[nt], qf[ks],
                         kf[nt >> 1][(nt & 1) * 2], kf[nt >> 1][(nt & 1) * 2 + 1]);
        }

        // ---- P = trunc(exp(S)), partial sums, warp-private smem ----
#pragma unroll
        for (int nt = 0; nt < 8; nt++) {
            const float t0 = trunc_tf32(__expf(sacc[nt][0]));
            const float t1 = trunc_tf32(__expf(sacc[nt][1]));
            const float t2 = trunc_tf32(__expf(sacc[nt][2]));
            const float t3 = trunc_tf32(__expf(sacc[nt][3]));
            l0 += t0 + t1;
            l1 += t2 + t3;
            *(float2*)(psmp + SW256(prow,     nt * 32 + pcb)) = make_float2(t0, t1);
            *(float2*)(psmp + SW256(prow + 8, nt * 32 + pcb)) = make_float2(t2, t3);
        }
        __syncwarp();

        // ---- O += P V ----
#pragma unroll
        for (int kc = 0; kc < 8; kc++) {
            uint32_t pf[4];
            ldsm_x4(pbase + SW256(ar, kc * 32 + ac), pf);
            uint32_t vf[4][4];
#pragma unroll
            for (int nbh = 0; nbh < 4; nbh++)
                ldsm_x4(sb + AT_VOFF + SW256(nbh * 16 + br, kc * 32 + bc), vf[nbh]);
#pragma unroll
            for (int nt = 0; nt < 8; nt++)
                mma_tf32(oacc[nt], pf,
                         vf[nt >> 1][(nt & 1) * 2], vf[nt >> 1][(nt & 1) * 2 + 1]);
        }
    }

    // ---- epilogue ----
    l0 += __shfl_xor_sync(0xffffffffu, l0, 1);
    l0 += __shfl_xor_sync(0xffffffffu, l0, 2);
    l1 += __shfl_xor_sync(0xffffffffu, l1, 1);
    l1 += __shfl_xor_sync(0xffffffffu, l1, 2);
    const float inv0 = 1.0f / l0;
    const float inv1 = 1.0f / l1;

    const size_t row0 = (size_t)b * L_ + q0 + wid * 16 + (lane >> 2);
    const size_t row1 = row0 + 8;
#pragma unroll
    for (int nt = 0; nt < 8; nt++) {
        const int col = h * HD_ + nt * 8 + (lane & 3) * 2;
        float2 v0; v0.x = rna(oacc[nt][0] * inv0); v0.y = rna(oacc[nt][1] * inv0);
        float2 v1; v1.x = rna(oacc[nt][2] * inv1); v1.y = rna(oacc[nt][3] * inv1);
        *(float2*)(O + row0 * D_ + col) = v0;
        *(float2*)(O + row1 * D_ + col) = v1;
    }
}

// ---------------------------------------------------------------------------
extern "C" void kernel_launch(void* const* d_in, const int* in_sizes, int n_in,
                              void* d_out, int out_size)
{
    const float* x  = (const float*)d_in[0];
    const float* Wq = (const float*)d_in[1];
    const float* bq = (const float*)d_in[2];
    const float* Wk = (const float*)d_in[3];
    const float* bk = (const float*)d_in[4];
    const float* Wv = (const float*)d_in[5];
    const float* bv = (const float*)d_in[6];
    const float* Wo = (const float*)d_in[7];
    const float* bo = (const float*)d_in[8];
    float* out = (float*)d_out;

    float *xt, *q, *k, *vt, *o, *wt;
    cudaGetSymbolAddress((void**)&xt, g_xt);
    cudaGetSymbolAddress((void**)&q,  g_q);
    cudaGetSymbolAddress((void**)&k,  g_k);
    cudaGetSymbolAddress((void**)&vt, g_vt);
    cudaGetSymbolAddress((void**)&o,  g_o);
    cudaGetSymbolAddress((void**)&wt, g_wt);
    const size_t WSZ = (size_t)D_ * D_;

    cudaFuncSetAttribute(mm_gemm<0>, cudaFuncAttributeMaxDynamicSharedMemorySize, G_DYN);
    cudaFuncSetAttribute(mm_gemm<1>, cudaFuncAttributeMaxDynamicSharedMemorySize, G_DYN);
    cudaFuncSetAttribute(mm_gemm<2>, cudaFuncAttributeMaxDynamicSharedMemorySize, G_DYN);
    cudaFuncSetAttribute(attn_tf32,  cudaFuncAttributeMaxDynamicSharedMemorySize, AT_DYN);

    dim3 ggrid(D_ / 128, M_ / 128);   // (6, 64)

    // 1. fused preprocessing (round x + transpose/round all 4 weights)
    preprocess<<<RX_BLOCKS + 4 * TP_BLOCKS_PER_W, 256>>>(x, xt, Wq, Wk, Wv, Wo, wt);

    // 2-4. projections (Q pre-scaled 1/8; V written transposed)
    mm_gemm<1><<<ggrid, 256, G_DYN>>>(xt, wt + 0 * WSZ, bq, 0.125f, q);
    mm_gemm<1><<<ggrid, 256, G_DYN>>>(xt, wt + 1 * WSZ, bk, 1.0f,  k);
    mm_gemm<2><<<ggrid, 256, G_DYN>>>(xt, wt + 2 * WSZ, bv, 1.0f,  vt);

    // 5. attention (lands in the ncu capture window)
    attn_tf32<<<dim3(L_ / 128, H_, B_), 256, AT_DYN>>>(q, k, vt, o);

    // 6. output projection
    mm_gemm<0><<<ggrid, 256, G_DYN>>>(o, wt + 3 * WSZ, bo, 1.0f, out);
}

// round 10
// speedup vs baseline: 1.3054x; 1.3054x over previous
#include <cuda_runtime.h>
#include <math.h>
#include <stdint.h>

#define B_  4
#define L_  2048
#define D_  768
#define H_  12
#define HD_ 64
#define M_  (B_*L_)

// ---------------------------------------------------------------------------
// Scratch (device globals; all values tf32-rounded fp32)
// ---------------------------------------------------------------------------
__device__ float g_xt[(size_t)M_*D_];    // x rounded
__device__ float g_q [(size_t)M_*D_];    // [B,H,L,hd], pre-scaled 1/8
__device__ float g_k [(size_t)M_*D_];    // [B,H,L,hd]
__device__ float g_vt[(size_t)M_*D_];    // [B,H,hd,L]  (transposed!)
__device__ float g_o [(size_t)M_*D_];    // [M,D] attention output
__device__ float g_wt[4][(size_t)D_*D_]; // W^T rounded (q,k,v,o)

// ---------------------------------------------------------------------------
// Baseline-PTX helpers (sm_80-era: valid at target sm_103)
// ---------------------------------------------------------------------------
__device__ __forceinline__ uint32_t smem_to_u32(const void* p) {
    uint32_t a;
    asm("{ .reg .u64 t; cvta.to.shared.u64 t, %1; cvt.u32.u64 %0, t; }"
        : "=r"(a) : "l"(p));
    return a;
}
__device__ __forceinline__ void ldsm_x4(uint32_t addr, uint32_t* r) {
    asm volatile("ldmatrix.sync.aligned.m8n8.x4.shared.b16 {%0,%1,%2,%3}, [%4];"
                 : "=r"(r[0]), "=r"(r[1]), "=r"(r[2]), "=r"(r[3]) : "r"(addr));
}
__device__ __forceinline__ void mma_tf32(float* c, const uint32_t* a,
                                         const uint32_t b0, const uint32_t b1) {
    asm volatile("mma.sync.aligned.m16n8k8.row.col.f32.tf32.tf32.f32 "
                 "{%0,%1,%2,%3}, {%4,%5,%6,%7}, {%8,%9}, {%0,%1,%2,%3};"
                 : "+f"(c[0]), "+f"(c[1]), "+f"(c[2]), "+f"(c[3])
                 : "r"(a[0]), "r"(a[1]), "r"(a[2]), "r"(a[3]), "r"(b0), "r"(b1));
}
__device__ __forceinline__ float rna(float x) {
    uint32_t u;
    asm("cvt.rna.tf32.f32 %0, %1;" : "=r"(u) : "f"(x));
    return __uint_as_float(u);
}
__device__ __forceinline__ float trunc_tf32(float x) {
    return __uint_as_float(__float_as_uint(x) & 0xFFFFE000u);
}
#define CP_ASYNC16(saddr, gptr) \
    asm volatile("cp.async.cg.shared.global [%0], [%1], 16;" \
                 :: "r"(saddr), "l"(gptr))
#define CP_COMMIT()  asm volatile("cp.async.commit_group;" ::: "memory")
#define CP_WAIT(N)   asm volatile("cp.async.wait_group %0;" :: "n"(N) : "memory")

// 256B-row swizzle: XOR 16B-chunk bits [4:7) with row bits [0:3)
#define SW256(row, cb) ((uint32_t)((row) * 256 + ((cb) ^ (((row) & 7) << 4))))

// ---------------------------------------------------------------------------
// Preprocessing (two launches so attn lands in the ncu capture window)
// ---------------------------------------------------------------------------
__global__ __launch_bounds__(256)
void pre_x(const float* __restrict__ src, float* __restrict__ dst)
{
    size_t i = ((size_t)blockIdx.x * 256 + threadIdx.x) * 4;
    float4 v = *(const float4*)(src + i);
    v.x = rna(v.x); v.y = rna(v.y); v.z = rna(v.z); v.w = rna(v.w);
    *(float4*)(dst + i) = v;
}

__global__ __launch_bounds__(256)
void pre_w(const float* __restrict__ W0, const float* __restrict__ W1,
           const float* __restrict__ W2, const float* __restrict__ W3,
           float* __restrict__ wt)
{
    __shared__ float t[32][33];
    const int w = blockIdx.z;
    const float* W = (w == 0) ? W0 : (w == 1) ? W1 : (w == 2) ? W2 : W3;
    float* WT = wt + (size_t)w * D_ * D_;
    const int tx = threadIdx.x & 31, ty = threadIdx.x >> 5;   // 32 x 8
    const int x0 = blockIdx.x * 32, y0 = blockIdx.y * 32;
#pragma unroll
    for (int i = 0; i < 32; i += 8)
        t[ty + i][tx] = W[(size_t)(y0 + ty + i) * D_ + x0 + tx];
    __syncthreads();
#pragma unroll
    for (int i = 0; i < 32; i += 8)
        WT[(size_t)(x0 + ty + i) * D_ + y0 + tx] = rna(t[tx][ty + i]);
}

// ---------------------------------------------------------------------------
// tf32 GEMM body (R7 config: K-chunks of 64 floats / 256B rows, 2-stage).
// 128x128 CTA tile, 8 warps (2m x 4n), warp 64x32.
// ---------------------------------------------------------------------------
#define G_STAGE 65536
#define G_OFF_B 32768
#define G_DYN   (2 * G_STAGE + 1024)

// Shared GEMM mainloop: computes acc for tile (m0,n0) of A @ Bt^T, then
// calls the epilogue functor per (m, col) fragment pair.
template<typename EpilogueFn>
__device__ __forceinline__
void gemm_core(const float* __restrict__ A, const float* __restrict__ Bt,
               int m0, int n0, uint32_t base, EpilogueFn epi)
{
    const int tid  = threadIdx.x;
    const int wid  = tid >> 5;
    const int lane = tid & 31;
    const int wm   = wid & 1;
    const int wn   = wid >> 1;

    const int lrow = tid >> 1;
    const int lcb0 = (tid & 1) * 128;
    const float* gA = A  + (size_t)(m0 + lrow) * D_ + (lcb0 >> 2);
    const float* gB = Bt + (size_t)(n0 + lrow) * D_ + (lcb0 >> 2);

    const int arow = wm * 64 + (lane & 7) + ((lane >> 3) & 1) * 8;
    const int acb  = (lane >> 4) * 16;
    const int brow = wn * 32 + (lane & 7) + ((lane >> 4) & 1) * 8;
    const int bcb  = ((lane >> 3) & 1) * 16;

    float acc[4][4][4];
#pragma unroll
    for (int mi = 0; mi < 4; mi++)
#pragma unroll
        for (int nt = 0; nt < 4; nt++)
#pragma unroll
            for (int c = 0; c < 4; c++) acc[mi][nt][c] = 0.0f;

    const int NCHUNK = D_ / 64;   // 12

    // load chunk 0 into stage 0
    {
        const uint32_t sb = base;
#pragma unroll
        for (int c = 0; c < 8; c++) {
            const uint32_t so = SW256(lrow, lcb0 + c * 16);
            CP_ASYNC16(sb + so,           gA + c * 4);
            CP_ASYNC16(sb + G_OFF_B + so, gB + c * 4);
        }
    }
    CP_COMMIT();

    for (int i = 0; i < NCHUNK; i++) {
        if (i + 1 < NCHUNK) {
            const uint32_t sb = base + (uint32_t)((i + 1) & 1) * G_STAGE;
            const int kf = (i + 1) * 64;
#pragma unroll
            for (int c = 0; c < 8; c++) {
                const uint32_t so = SW256(lrow, lcb0 + c * 16);
                CP_ASYNC16(sb + so,           gA + kf + c * 4);
                CP_ASYNC16(sb + G_OFF_B + so, gB + kf + c * 4);
            }
            CP_COMMIT();
            CP_WAIT(1);
        } else {
            CP_WAIT(0);
        }
        __syncthreads();

        const uint32_t sb = base + (uint32_t)(i & 1) * G_STAGE;
#pragma unroll
        for (int ks = 0; ks < 8; ks++) {
            uint32_t a[4][4], bf[2][4];
#pragma unroll
            for (int mi = 0; mi < 4; mi++)
                ldsm_x4(sb + SW256(arow + mi * 16, acb + ks * 32), a[mi]);
#pragma unroll
            for (int nbh = 0; nbh < 2; nbh++)
                ldsm_x4(sb + G_OFF_B + SW256(brow + nbh * 16, bcb + ks * 32), bf[nbh]);
#pragma unroll
            for (int mi = 0; mi < 4; mi++)
#pragma unroll
                for (int nt = 0; nt < 4; nt++)
                    mma_tf32(acc[mi][nt], a[mi],
                             bf[nt >> 1][(nt & 1) * 2], bf[nt >> 1][(nt & 1) * 2 + 1]);
        }
        __syncthreads();
    }

    // epilogue: per-fragment callback (plain lambda: implicitly device here)
    const int grp = lane >> 2;
    const int tig = lane & 3;
#pragma unroll
    for (int nt = 0; nt < 4; nt++) {
        const int col = n0 + wn * 32 + nt * 8 + tig * 2;
#pragma unroll
        for (int mi = 0; mi < 4; mi++)
#pragma unroll
            for (int half = 0; half < 2; half++) {
                const int m = m0 + wm * 64 + mi * 16 + grp + half * 8;
                epi(m, col, acc[mi][nt][half * 2 + 0], acc[mi][nt][half * 2 + 1]);
            }
    }
}

// Fused QKV projection: blockIdx.z selects {Wq->q, Wk->k, Wv->vt}.
__global__ __launch_bounds__(256)
void qkv_gemm(const float* __restrict__ A, const float* __restrict__ wt,
              const float* __restrict__ bq, const float* __restrict__ bk,
              const float* __restrict__ bv,
              float* __restrict__ Oq, float* __restrict__ Ok,
              float* __restrict__ Ovt)
{
    extern __shared__ char dsm[];
    const uint32_t raw  = smem_to_u32(dsm);
    const uint32_t base = (raw + 1023) & ~1023u;

    const int z = blockIdx.z;
    const float* Bt   = wt + (size_t)z * D_ * D_;
    const float* bias = (z == 0) ? bq : (z == 1) ? bk : bv;
    const float scale = (z == 0) ? 0.125f : 1.0f;
    float* Chl = (z == 0) ? Oq : Ok;

    const int m0 = blockIdx.y * 128;
    const int n0 = blockIdx.x * 128;

    gemm_core(A, Bt, m0, n0, base,
        [&](int m, int col, float a0, float a1) {
            const float v0 = (a0 + bias[col]) * scale;
            const float v1 = (a1 + bias[col + 1]) * scale;
            const int batch = m / L_, lr = m % L_;
            const int h = col / HD_, d0 = col % HD_;
            if (z < 2) {
                float2 v; v.x = rna(v0); v.y = rna(v1);
                *(float2*)(Chl + (((size_t)(batch * H_ + h) * L_ + lr) * HD_ + d0)) = v;
            } else {
                const size_t vb = ((size_t)(batch * H_ + h) * HD_ + d0) * L_ + lr;
                Ovt[vb]      = rna(v0);
                Ovt[vb + L_] = rna(v1);
            }
        });
}

// Output projection: fp32 [M,D] out.
__global__ __launch_bounds__(256)
void out_gemm(const float* __restrict__ A, const float* __restrict__ Bt,
              const float* __restrict__ bias, float* __restrict__ C)
{
    extern __shared__ char dsm[];
    const uint32_t raw  = smem_to_u32(dsm);
    const uint32_t base = (raw + 1023) & ~1023u;
    const int m0 = blockIdx.y * 128;
    const int n0 = blockIdx.x * 128;

    gemm_core(A, Bt, m0, n0, base,
        [&](int m, int col, float a0, float a1) {
            float2 v; v.x = a0 + bias[col]; v.y = a1 + bias[col + 1];
            *(float2*)(C + (size_t)m * D_ + col) = v;
        });
}

// ---------------------------------------------------------------------------
// tf32 flash attention (R7 config: 2-stage cp.async, warp-private P smem).
// 256 threads / 8 warps; warp = 16 q-rows x 64 kv tile. No online-max.
// ---------------------------------------------------------------------------
#define AT_P    32768
#define AT_STG  65536
#define AT_SSZ  32768
#define AT_VOFF 16384
#define AT_DYN  (AT_STG + 2 * AT_SSZ + 1024)

__global__ __launch_bounds__(256)
void attn_tf32(const float* __restrict__ Q, const float* __restrict__ K,
               const float* __restrict__ VT, float* __restrict__ O)
{
    extern __shared__ char dsm[];
    const uint32_t raw  = smem_to_u32(dsm);
    const uint32_t base = (raw + 1023) & ~1023u;
    char* smp = dsm + (base - raw);

    const int tid = threadIdx.x;
    const int wid = tid >> 5;
    const int lane = tid & 31;
    const int b = blockIdx.z, h = blockIdx.y;
    const int q0 = blockIdx.x * 128;
    const size_t hoff = (size_t)(b * H_ + h) * L_ * HD_;

    // Q load: 128 rows x 256B
    {
        const int r = tid >> 1, cb0 = (tid & 1) * 128;
        const float* g = Q + hoff + (size_t)(q0 + r) * HD_ + (cb0 >> 2);
#pragma unroll
        for (int c = 0; c < 8; c++)
            CP_ASYNC16(base + SW256(r, cb0 + c * 16), g + c * 4);
    }
    const int sr = tid >> 2, scb0 = (tid & 3) * 64;
    auto load_stage = [&](int kt, int stg) {
        const uint32_t sb = base + AT_STG + (uint32_t)stg * AT_SSZ;
        const float* gk = K  + hoff + (size_t)(kt + sr) * HD_ + (scb0 >> 2);
        const float* gv = VT + hoff + (size_t)sr * L_ + kt + (scb0 >> 2);
#pragma unroll
        for (int c = 0; c < 4; c++) {
            const uint32_t so = SW256(sr, scb0 + c * 16);
            CP_ASYNC16(sb + so,           gk + c * 4);
            CP_ASYNC16(sb + AT_VOFF + so, gv + c * 4);
        }
    };
    load_stage(0, 0);  CP_COMMIT();   // group0: Q + stage0
    load_stage(64, 1); CP_COMMIT();   // group1: stage1
    CP_WAIT(1);
    __syncthreads();

    const int ar = (lane & 7) + ((lane >> 3) & 1) * 8;
    const int ac = (lane >> 4) * 16;
    const int br = (lane & 7) + ((lane >> 4) & 1) * 8;
    const int bc = ((lane >> 3) & 1) * 16;

    // Q fragments (register-resident)
    uint32_t qf[8][4];
#pragma unroll
    for (int ks = 0; ks < 8; ks++)
        ldsm_x4(base + SW256(wid * 16 + ar, ks * 32 + ac), qf[ks]);

    float oacc[8][4];
#pragma unroll
    for (int nt = 0; nt < 8; nt++)
#pragma unroll
        for (int c = 0; c < 4; c++) oacc[nt][c] = 0.0f;
    float l0 = 0.0f, l1 = 0.0f;

    const uint32_t pbase = base + AT_P + (uint32_t)wid * 4096;
    char* psmp = smp + AT_P + wid * 4096;
    const int prow = lane >> 2;
    const int pcb  = (lane & 3) * 8;

    const int NIT = L_ / 64;   // 32
    for (int it = 0; it < NIT; it++) {
        const uint32_t sb = base + AT_STG + (uint32_t)(it & 1) * AT_SSZ;

        // ---- S = Q K^T ----
        float sacc[8][4];
#pragma unroll
        for (int nt = 0; nt < 8; nt++)
#pragma unroll
            for (int c = 0; c < 4; c++) sacc[nt][c] = 0.0f;
#pragma unroll
        for (int ks = 0; ks < 8; ks++) {
            uint32_t kf[4][4];
#pragma unroll
            for (int nbh = 0; nbh < 4; nbh++)
                ldsm_x4(sb + SW256(nbh * 16 + br, ks * 32 + bc), kf[nbh]);
#pragma unroll
            for (int nt = 0; nt < 8; nt++)
                mma_tf32(sacc[nt], qf[ks],
                         kf[nt >> 1][(nt & 1) * 2], kf[nt >> 1][(nt & 1) * 2 + 1]);
        }

        // ---- P = trunc(exp(S)), partial sums, warp-private smem ----
#pragma unroll
        for (int nt = 0; nt < 8; nt++) {
            const float t0 = trunc_tf32(__expf(sacc[nt][0]));
            const float t1 = trunc_tf32(__expf(sacc[nt][1]));
            const float t2 = trunc_tf32(__expf(sacc[nt][2]));
            const float t3 = trunc_tf32(__expf(sacc[nt][3]));
            l0 += t0 + t1;
            l1 += t2 + t3;
            *(float2*)(psmp + SW256(prow,     nt * 32 + pcb)) = make_float2(t0, t1);
            *(float2*)(psmp + SW256(prow + 8, nt * 32 + pcb)) = make_float2(t2, t3);
        }
        __syncwarp();

        // ---- O += P V ----
#pragma unroll
        for (int kc = 0; kc < 8; kc++) {
            uint32_t pf[4];
            ldsm_x4(pbase + SW256(ar, kc * 32 + ac), pf);
            uint32_t vf[4][4];
#pragma unroll
            for (int nbh = 0; nbh < 4; nbh++)
                ldsm_x4(sb + AT_VOFF + SW256(nbh * 16 + br, kc * 32 + bc), vf[nbh]);
#pragma unroll
            for (int nt = 0; nt < 8; nt++)
                mma_tf32(oacc[nt], pf,
                         vf[nt >> 1][(nt & 1) * 2], vf[nt >> 1][(nt & 1) * 2 + 1]);
        }

        // ---- pipeline ----
        __syncthreads();
        if (it + 2 < NIT) load_stage((it + 2) * 64, it & 1);
        CP_COMMIT();
        if (it + 1 < NIT) {
            CP_WAIT(1);
            __syncthreads();
        }
    }

    // ---- epilogue ----
    l0 += __shfl_xor_sync(0xffffffffu, l0, 1);
    l0 += __shfl_xor_sync(0xffffffffu, l0, 2);
    l1 += __shfl_xor_sync(0xffffffffu, l1, 1);
    l1 += __shfl_xor_sync(0xffffffffu, l1, 2);
    const float inv0 = 1.0f / l0;
    const float inv1 = 1.0f / l1;

    const size_t row0 = (size_t)b * L_ + q0 + wid * 16 + (lane >> 2);
    const size_t row1 = row0 + 8;
#pragma unroll
    for (int nt = 0; nt < 8; nt++) {
        const int col = h * HD_ + nt * 8 + (lane & 3) * 2;
        float2 v0; v0.x = rna(oacc[nt][0] * inv0); v0.y = rna(oacc[nt][1] * inv0);
        float2 v1; v1.x = rna(oacc[nt][2] * inv1); v1.y = rna(oacc[nt][3] * inv1);
        *(float2*)(O + row0 * D_ + col) = v0;
        *(float2*)(O + row1 * D_ + col) = v1;
    }
}

// ---------------------------------------------------------------------------
extern "C" void kernel_launch(void* const* d_in, const int* in_sizes, int n_in,
                              void* d_out, int out_size)
{
    const float* x  = (const float*)d_in[0];
    const float* Wq = (const float*)d_in[1];
    const float* bq = (const float*)d_in[2];
    const float* Wk = (const float*)d_in[3];
    const float* bk = (const float*)d_in[4];
    const float* Wv = (const float*)d_in[5];
    const float* bv = (const float*)d_in[6];
    const float* Wo = (const float*)d_in[7];
    const float* bo = (const float*)d_in[8];
    float* out = (float*)d_out;

    float *xt, *q, *k, *vt, *o, *wt;
    cudaGetSymbolAddress((void**)&xt, g_xt);
    cudaGetSymbolAddress((void**)&q,  g_q);
    cudaGetSymbolAddress((void**)&k,  g_k);
    cudaGetSymbolAddress((void**)&vt, g_vt);
    cudaGetSymbolAddress((void**)&o,  g_o);
    cudaGetSymbolAddress((void**)&wt, g_wt);
    const size_t WSZ = (size_t)D_ * D_;

    cudaFuncSetAttribute(qkv_gemm,  cudaFuncAttributeMaxDynamicSharedMemorySize, G_DYN);
    cudaFuncSetAttribute(out_gemm,  cudaFuncAttributeMaxDynamicSharedMemorySize, G_DYN);
    cudaFuncSetAttribute(attn_tf32, cudaFuncAttributeMaxDynamicSharedMemorySize, AT_DYN);

    // 1-2. preprocessing
    pre_x<<<(M_ * D_) / 1024, 256>>>(x, xt);
    pre_w<<<dim3(D_ / 32, D_ / 32, 4), 256>>>(Wq, Wk, Wv, Wo, wt);

    // 3. fused QKV projections (single launch, 1152 CTAs)
    qkv_gemm<<<dim3(D_ / 128, M_ / 128, 3), 256, G_DYN>>>(
        xt, wt, bq, bk, bv, q, k, vt);

    // 4. attention (ncu capture window)
    attn_tf32<<<dim3(L_ / 128, H_, B_), 256, AT_DYN>>>(q, k, vt, o);

    // 5. output projection
    out_gemm<<<dim3(D_ / 128, M_ / 128), 256, G_DYN>>>(o, wt + 3 * WSZ, bo, out);
}

// round 11
// speedup vs baseline: 1.4269x; 1.0931x over previous
#include <cuda_runtime.h>
#include <math.h>
#include <stdint.h>

#define B_  4
#define L_  2048
#define D_  768
#define H_  12
#define HD_ 64
#define M_  (B_*L_)

// ---------------------------------------------------------------------------
// Scratch (device globals; all values tf32-rounded fp32)
// ---------------------------------------------------------------------------
__device__ float g_xt[(size_t)M_*D_];    // x rounded
__device__ float g_q [(size_t)M_*D_];    // [B,H,L,hd], pre-scaled 1/8
__device__ float g_k [(size_t)M_*D_];    // [B,H,L,hd]
__device__ float g_vt[(size_t)M_*D_];    // [B,H,hd,L]  (transposed!)
__device__ float g_o [(size_t)M_*D_];    // [M,D] attention output
__device__ float g_wt[4][(size_t)D_*D_]; // W^T rounded (q,k,v,o)

// ---------------------------------------------------------------------------
// Baseline-PTX helpers (sm_80-era: valid at target sm_103)
// ---------------------------------------------------------------------------
__device__ __forceinline__ uint32_t smem_to_u32(const void* p) {
    uint32_t a;
    asm("{ .reg .u64 t; cvta.to.shared.u64 t, %1; cvt.u32.u64 %0, t; }"
        : "=r"(a) : "l"(p));
    return a;
}
__device__ __forceinline__ void ldsm_x4(uint32_t addr, uint32_t* r) {
    asm volatile("ldmatrix.sync.aligned.m8n8.x4.shared.b16 {%0,%1,%2,%3}, [%4];"
                 : "=r"(r[0]), "=r"(r[1]), "=r"(r[2]), "=r"(r[3]) : "r"(addr));
}
__device__ __forceinline__ void mma_tf32(float* c, const uint32_t* a,
                                         const uint32_t b0, const uint32_t b1) {
    asm volatile("mma.sync.aligned.m16n8k8.row.col.f32.tf32.tf32.f32 "
                 "{%0,%1,%2,%3}, {%4,%5,%6,%7}, {%8,%9}, {%0,%1,%2,%3};"
                 : "+f"(c[0]), "+f"(c[1]), "+f"(c[2]), "+f"(c[3])
                 : "r"(a[0]), "r"(a[1]), "r"(a[2]), "r"(a[3]), "r"(b0), "r"(b1));
}
__device__ __forceinline__ float rna(float x) {
    uint32_t u;
    asm("cvt.rna.tf32.f32 %0, %1;" : "=r"(u) : "f"(x));
    return __uint_as_float(u);
}
__device__ __forceinline__ float trunc_tf32(float x) {
    return __uint_as_float(__float_as_uint(x) & 0xFFFFE000u);
}
#define CP_ASYNC16(saddr, gptr) \
    asm volatile("cp.async.cg.shared.global [%0], [%1], 16;" \
                 :: "r"(saddr), "l"(gptr))
#define CP_COMMIT()  asm volatile("cp.async.commit_group;" ::: "memory")
#define CP_WAIT(N)   asm volatile("cp.async.wait_group %0;" :: "n"(N) : "memory")

// 256B-row swizzle: XOR 16B-chunk bits [4:7) with row bits [0:3)
#define SW256(row, cb) ((uint32_t)((row) * 256 + ((cb) ^ (((row) & 7) << 4))))

// ---------------------------------------------------------------------------
// Preprocessing
// ---------------------------------------------------------------------------
__global__ __launch_bounds__(256)
void pre_x(const float* __restrict__ src, float* __restrict__ dst)
{
    size_t i = ((size_t)blockIdx.x * 256 + threadIdx.x) * 4;
    float4 v = *(const float4*)(src + i);
    v.x = rna(v.x); v.y = rna(v.y); v.z = rna(v.z); v.w = rna(v.w);
    *(float4*)(dst + i) = v;
}

__global__ __launch_bounds__(256)
void pre_w(const float* __restrict__ W0, const float* __restrict__ W1,
           const float* __restrict__ W2, const float* __restrict__ W3,
           float* __restrict__ wt)
{
    __shared__ float t[32][33];
    const int w = blockIdx.z;
    const float* W = (w == 0) ? W0 : (w == 1) ? W1 : (w == 2) ? W2 : W3;
    float* WT = wt + (size_t)w * D_ * D_;
    const int tx = threadIdx.x & 31, ty = threadIdx.x >> 5;   // 32 x 8
    const int x0 = blockIdx.x * 32, y0 = blockIdx.y * 32;
#pragma unroll
    for (int i = 0; i < 32; i += 8)
        t[ty + i][tx] = W[(size_t)(y0 + ty + i) * D_ + x0 + tx];
    __syncthreads();
#pragma unroll
    for (int i = 0; i < 32; i += 8)
        WT[(size_t)(x0 + ty + i) * D_ + y0 + tx] = rna(t[tx][ty + i]);
}

// ---------------------------------------------------------------------------
// tf32 GEMM body (R7 config: K-chunks of 64 floats / 256B rows, 2-stage).
// 128x128 CTA tile, 8 warps (2m x 4n), warp 64x32.
// ---------------------------------------------------------------------------
#define G_STAGE 65536
#define G_OFF_B 32768
#define G_DYN   (2 * G_STAGE + 1024)

template<typename EpilogueFn>
__device__ __forceinline__
void gemm_core(const float* __restrict__ A, const float* __restrict__ Bt,
               int m0, int n0, uint32_t base, EpilogueFn epi)
{
    const int tid  = threadIdx.x;
    const int wid  = tid >> 5;
    const int lane = tid & 31;
    const int wm   = wid & 1;
    const int wn   = wid >> 1;

    const int lrow = tid >> 1;
    const int lcb0 = (tid & 1) * 128;
    const float* gA = A  + (size_t)(m0 + lrow) * D_ + (lcb0 >> 2);
    const float* gB = Bt + (size_t)(n0 + lrow) * D_ + (lcb0 >> 2);

    const int arow = wm * 64 + (lane & 7) + ((lane >> 3) & 1) * 8;
    const int acb  = (lane >> 4) * 16;
    const int brow = wn * 32 + (lane & 7) + ((lane >> 4) & 1) * 8;
    const int bcb  = ((lane >> 3) & 1) * 16;

    float acc[4][4][4];
#pragma unroll
    for (int mi = 0; mi < 4; mi++)
#pragma unroll
        for (int nt = 0; nt < 4; nt++)
#pragma unroll
            for (int c = 0; c < 4; c++) acc[mi][nt][c] = 0.0f;

    const int NCHUNK = D_ / 64;   // 12

    {
        const uint32_t sb = base;
#pragma unroll
        for (int c = 0; c < 8; c++) {
            const uint32_t so = SW256(lrow, lcb0 + c * 16);
            CP_ASYNC16(sb + so,           gA + c * 4);
            CP_ASYNC16(sb + G_OFF_B + so, gB + c * 4);
        }
    }
    CP_COMMIT();

    for (int i = 0; i < NCHUNK; i++) {
        if (i + 1 < NCHUNK) {
            const uint32_t sb = base + (uint32_t)((i + 1) & 1) * G_STAGE;
            const int kf = (i + 1) * 64;
#pragma unroll
            for (int c = 0; c < 8; c++) {
                const uint32_t so = SW256(lrow, lcb0 + c * 16);
                CP_ASYNC16(sb + so,           gA + kf + c * 4);
                CP_ASYNC16(sb + G_OFF_B + so, gB + kf + c * 4);
            }
            CP_COMMIT();
            CP_WAIT(1);
        } else {
            CP_WAIT(0);
        }
        __syncthreads();

        const uint32_t sb = base + (uint32_t)(i & 1) * G_STAGE;
#pragma unroll
        for (int ks = 0; ks < 8; ks++) {
            uint32_t a[4][4], bf[2][4];
#pragma unroll
            for (int mi = 0; mi < 4; mi++)
                ldsm_x4(sb + SW256(arow + mi * 16, acb + ks * 32), a[mi]);
#pragma unroll
            for (int nbh = 0; nbh < 2; nbh++)
                ldsm_x4(sb + G_OFF_B + SW256(brow + nbh * 16, bcb + ks * 32), bf[nbh]);
#pragma unroll
            for (int mi = 0; mi < 4; mi++)
#pragma unroll
                for (int nt = 0; nt < 4; nt++)
                    mma_tf32(acc[mi][nt], a[mi],
                             bf[nt >> 1][(nt & 1) * 2], bf[nt >> 1][(nt & 1) * 2 + 1]);
        }
        __syncthreads();
    }

    const int grp = lane >> 2;
    const int tig = lane & 3;
#pragma unroll
    for (int nt = 0; nt < 4; nt++) {
        const int col = n0 + wn * 32 + nt * 8 + tig * 2;
#pragma unroll
        for (int mi = 0; mi < 4; mi++)
#pragma unroll
            for (int half = 0; half < 2; half++) {
                const int m = m0 + wm * 64 + mi * 16 + grp + half * 8;
                epi(m, col, acc[mi][nt][half * 2 + 0], acc[mi][nt][half * 2 + 1]);
            }
    }
}

__global__ __launch_bounds__(256)
void qkv_gemm(const float* __restrict__ A, const float* __restrict__ wt,
              const float* __restrict__ bq, const float* __restrict__ bk,
              const float* __restrict__ bv,
              float* __restrict__ Oq, float* __restrict__ Ok,
              float* __restrict__ Ovt)
{
    extern __shared__ char dsm[];
    const uint32_t raw  = smem_to_u32(dsm);
    const uint32_t base = (raw + 1023) & ~1023u;

    const int z = blockIdx.z;
    const float* Bt   = wt + (size_t)z * D_ * D_;
    const float* bias = (z == 0) ? bq : (z == 1) ? bk : bv;
    const float scale = (z == 0) ? 0.125f : 1.0f;
    float* Chl = (z == 0) ? Oq : Ok;

    const int m0 = blockIdx.y * 128;
    const int n0 = blockIdx.x * 128;

    gemm_core(A, Bt, m0, n0, base,
        [&](int m, int col, float a0, float a1) {
            const float v0 = (a0 + bias[col]) * scale;
            const float v1 = (a1 + bias[col + 1]) * scale;
            const int batch = m / L_, lr = m % L_;
            const int h = col / HD_, d0 = col % HD_;
            if (z < 2) {
                float2 v; v.x = rna(v0); v.y = rna(v1);
                *(float2*)(Chl + (((size_t)(batch * H_ + h) * L_ + lr) * HD_ + d0)) = v;
            } else {
                const size_t vb = ((size_t)(batch * H_ + h) * HD_ + d0) * L_ + lr;
                Ovt[vb]      = rna(v0);
                Ovt[vb + L_] = rna(v1);
            }
        });
}

__global__ __launch_bounds__(256)
void out_gemm(const float* __restrict__ A, const float* __restrict__ Bt,
              const float* __restrict__ bias, float* __restrict__ C)
{
    extern __shared__ char dsm[];
    const uint32_t raw  = smem_to_u32(dsm);
    const uint32_t base = (raw + 1023) & ~1023u;
    const int m0 = blockIdx.y * 128;
    const int n0 = blockIdx.x * 128;

    gemm_core(A, Bt, m0, n0, base,
        [&](int m, int col, float a0, float a1) {
            float2 v; v.x = a0 + bias[col]; v.y = a1 + bias[col + 1];
            *(float2*)(C + (size_t)m * D_ + col) = v;
        });
}

// ---------------------------------------------------------------------------
// tf32 flash attention, WIDE warp tile: 32 q-rows x 64 kv per warp.
// CTA = 256 q-rows, 8 warps, grid 384. Q in smem (re-read per ks, frees
// regs); K/V 2-stage cp.async; P via warp-private smem (tf32-truncated,
// l summed from same truncated values). K/V fragment loads amortized over
// 2x more MMAs: 96 ldsm / 512 mma vs 144/256 before (-33% L1 per mma).
// ---------------------------------------------------------------------------
#define AT_Q    0
#define AT_P    65536
#define AT_STG  131072
#define AT_SSZ  32768
#define AT_VOFF 16384
#define AT_DYN  (AT_STG + 2 * AT_SSZ + 1024)

__global__ __launch_bounds__(256)
void attn_tf32(const float* __restrict__ Q, const float* __restrict__ K,
               const float* __restrict__ VT, float* __restrict__ O)
{
    extern __shared__ char dsm[];
    const uint32_t raw  = smem_to_u32(dsm);
    const uint32_t base = (raw + 1023) & ~1023u;
    char* smp = dsm + (base - raw);

    const int tid = threadIdx.x;
    const int wid = tid >> 5;
    const int lane = tid & 31;
    const int b = blockIdx.z, h = blockIdx.y;
    const int q0 = blockIdx.x * 256;
    const size_t hoff = (size_t)(b * H_ + h) * L_ * HD_;

    // Q load: 256 rows x 256B (each thread: 1 row, 16 chunks)
    {
        const float* g = Q + hoff + (size_t)(q0 + tid) * HD_;
#pragma unroll
        for (int c = 0; c < 16; c++)
            CP_ASYNC16(base + AT_Q + SW256(tid, c * 16), g + c * 4);
    }
    const int sr = tid >> 2, scb0 = (tid & 3) * 64;
    auto load_stage = [&](int kt, int stg) {
        const uint32_t sb = base + AT_STG + (uint32_t)stg * AT_SSZ;
        const float* gk = K  + hoff + (size_t)(kt + sr) * HD_ + (scb0 >> 2);
        const float* gv = VT + hoff + (size_t)sr * L_ + kt + (scb0 >> 2);
#pragma unroll
        for (int c = 0; c < 4; c++) {
            const uint32_t so = SW256(sr, scb0 + c * 16);
            CP_ASYNC16(sb + so,           gk + c * 4);
            CP_ASYNC16(sb + AT_VOFF + so, gv + c * 4);
        }
    };
    load_stage(0, 0);  CP_COMMIT();   // group0: Q + stage0
    load_stage(64, 1); CP_COMMIT();   // group1: stage1
    CP_WAIT(1);
    __syncthreads();

    const int ar = (lane & 7) + ((lane >> 3) & 1) * 8;   // A-pattern row
    const int ac = (lane >> 4) * 16;                     // A-pattern col byte
    const int br = (lane & 7) + ((lane >> 4) & 1) * 8;   // B-pattern row
    const int bc = ((lane >> 3) & 1) * 16;               // B-pattern col byte

    float oacc[2][8][4];
#pragma unroll
    for (int qi = 0; qi < 2; qi++)
#pragma unroll
        for (int nt = 0; nt < 8; nt++)
#pragma unroll
            for (int c = 0; c < 4; c++) oacc[qi][nt][c] = 0.0f;
    float lsum[2][2] = {{0.0f, 0.0f}, {0.0f, 0.0f}};

    const uint32_t qrow0 = (uint32_t)(wid * 32);
    const uint32_t pbase = base + AT_P + (uint32_t)wid * 8192;
    char* psmp = smp + AT_P + wid * 8192;
    const int prow = lane >> 2;
    const int pcb  = (lane & 3) * 8;

    const int NIT = L_ / 64;   // 32
    for (int it = 0; it < NIT; it++) {
        const uint32_t sb = base + AT_STG + (uint32_t)(it & 1) * AT_SSZ;

        // ---- S = Q K^T (32 q-rows per warp) ----
        float sacc[2][8][4];
#pragma unroll
        for (int qi = 0; qi < 2; qi++)
#pragma unroll
            for (int nt = 0; nt < 8; nt++)
#pragma unroll
                for (int c = 0; c < 4; c++) sacc[qi][nt][c] = 0.0f;
#pragma unroll
        for (int ks = 0; ks < 8; ks++) {
            uint32_t qa[2][4];
#pragma unroll
            for (int qi = 0; qi < 2; qi++)
                ldsm_x4(base + AT_Q + SW256(qrow0 + qi * 16 + ar, ks * 32 + ac), qa[qi]);
            uint32_t kf[4][4];
#pragma unroll
            for (int nbh = 0; nbh < 4; nbh++)
                ldsm_x4(sb + SW256(nbh * 16 + br, ks * 32 + bc), kf[nbh]);
#pragma unroll
            for (int qi = 0; qi < 2; qi++)
#pragma unroll
                for (int nt = 0; nt < 8; nt++)
                    mma_tf32(sacc[qi][nt], qa[qi],
                             kf[nt >> 1][(nt & 1) * 2], kf[nt >> 1][(nt & 1) * 2 + 1]);
        }

        // ---- P = trunc(exp(S)), partial sums, warp-private smem ----
#pragma unroll
        for (int qi = 0; qi < 2; qi++)
#pragma unroll
            for (int nt = 0; nt < 8; nt++) {
                const float t0 = trunc_tf32(__expf(sacc[qi][nt][0]));
                const float t1 = trunc_tf32(__expf(sacc[qi][nt][1]));
                const float t2 = trunc_tf32(__expf(sacc[qi][nt][2]));
                const float t3 = trunc_tf32(__expf(sacc[qi][nt][3]));
                lsum[qi][0] += t0 + t1;
                lsum[qi][1] += t2 + t3;
                *(float2*)(psmp + SW256(qi * 16 + prow,     nt * 32 + pcb)) =
                    make_float2(t0, t1);
                *(float2*)(psmp + SW256(qi * 16 + prow + 8, nt * 32 + pcb)) =
                    make_float2(t2, t3);
            }
        __syncwarp();

        // ---- O += P V ----
#pragma unroll
        for (int kc = 0; kc < 8; kc++) {
            uint32_t pf[2][4];
#pragma unroll
            for (int qi = 0; qi < 2; qi++)
                ldsm_x4(pbase + SW256(qi * 16 + ar, kc * 32 + ac), pf[qi]);
            uint32_t vf[4][4];
#pragma unroll
            for (int nbh = 0; nbh < 4; nbh++)
                ldsm_x4(sb + AT_VOFF + SW256(nbh * 16 + br, kc * 32 + bc), vf[nbh]);
#pragma unroll
            for (int qi = 0; qi < 2; qi++)
#pragma unroll
                for (int nt = 0; nt < 8; nt++)
                    mma_tf32(oacc[qi][nt], pf[qi],
                             vf[nt >> 1][(nt & 1) * 2], vf[nt >> 1][(nt & 1) * 2 + 1]);
        }

        // ---- pipeline ----
        __syncthreads();
        if (it + 2 < NIT) load_stage((it + 2) * 64, it & 1);
        CP_COMMIT();
        if (it + 1 < NIT) {
            CP_WAIT(1);
            __syncthreads();
        }
    }

    // ---- epilogue ----
#pragma unroll
    for (int qi = 0; qi < 2; qi++)
#pragma unroll
        for (int hf = 0; hf < 2; hf++) {
            float s = lsum[qi][hf];
            s += __shfl_xor_sync(0xffffffffu, s, 1);
            s += __shfl_xor_sync(0xffffffffu, s, 2);
            lsum[qi][hf] = 1.0f / s;
        }

#pragma unroll
    for (int qi = 0; qi < 2; qi++) {
        const size_t row0 = (size_t)b * L_ + q0 + wid * 32 + qi * 16 + (lane >> 2);
        const size_t row1 = row0 + 8;
        const float inv0 = lsum[qi][0];
        const float inv1 = lsum[qi][1];
#pragma unroll
        for (int nt = 0; nt < 8; nt++) {
            const int col = h * HD_ + nt * 8 + (lane & 3) * 2;
            float2 v0; v0.x = rna(oacc[qi][nt][0] * inv0); v0.y = rna(oacc[qi][nt][1] * inv0);
            float2 v1; v1.x = rna(oacc[qi][nt][2] * inv1); v1.y = rna(oacc[qi][nt][3] * inv1);
            *(float2*)(O + row0 * D_ + col) = v0;
            *(float2*)(O + row1 * D_ + col) = v1;
        }
    }
}

// ---------------------------------------------------------------------------
extern "C" void kernel_launch(void* const* d_in, const int* in_sizes, int n_in,
                              void* d_out, int out_size)
{
    const float* x  = (const float*)d_in[0];
    const float* Wq = (const float*)d_in[1];
    const float* bq = (const float*)d_in[2];
    const float* Wk = (const float*)d_in[3];
    const float* bk = (const float*)d_in[4];
    const float* Wv = (const float*)d_in[5];
    const float* bv = (const float*)d_in[6];
    const float* Wo = (const float*)d_in[7];
    const float* bo = (const float*)d_in[8];
    float* out = (float*)d_out;

    float *xt, *q, *k, *vt, *o, *wt;
    cudaGetSymbolAddress((void**)&xt, g_xt);
    cudaGetSymbolAddress((void**)&q,  g_q);
    cudaGetSymbolAddress((void**)&k,  g_k);
    cudaGetSymbolAddress((void**)&vt, g_vt);
    cudaGetSymbolAddress((void**)&o,  g_o);
    cudaGetSymbolAddress((void**)&wt, g_wt);
    const size_t WSZ = (size_t)D_ * D_;

    cudaFuncSetAttribute(qkv_gemm,  cudaFuncAttributeMaxDynamicSharedMemorySize, G_DYN);
    cudaFuncSetAttribute(out_gemm,  cudaFuncAttributeMaxDynamicSharedMemorySize, G_DYN);
    cudaFuncSetAttribute(attn_tf32, cudaFuncAttributeMaxDynamicSharedMemorySize, AT_DYN);

    // 1-2. preprocessing
    pre_x<<<(M_ * D_) / 1024, 256>>>(x, xt);
    pre_w<<<dim3(D_ / 32, D_ / 32, 4), 256>>>(Wq, Wk, Wv, Wo, wt);

    // 3. fused QKV projections (single launch, 1152 CTAs)
    qkv_gemm<<<dim3(D_ / 128, M_ / 128, 3), 256, G_DYN>>>(
        xt, wt, bq, bk, bv, q, k, vt);

    // 4. attention (wide warp tile; ncu capture window)
    attn_tf32<<<dim3(L_ / 256, H_, B_), 256, AT_DYN>>>(q, k, vt, o);

    // 5. output projection
    out_gemm<<<dim3(D_ / 128, M_ / 128), 256, G_DYN>>>(o, wt + 3 * WSZ, bo, out);
}

// round 12
// speedup vs baseline: 1.5674x; 1.0985x over previous
#include <cuda_runtime.h>
#include <math.h>
#include <stdint.h>

#define B_  4
#define L_  2048
#define D_  768
#define H_  12
#define HD_ 64
#define M_  (B_*L_)

// ---------------------------------------------------------------------------
// Scratch (device globals; all values tf32-rounded fp32)
// ---------------------------------------------------------------------------
__device__ float g_q [(size_t)M_*D_];    // [B,H,L,hd], pre-scaled 1/8
__device__ float g_k [(size_t)M_*D_];    // [B,H,L,hd]
__device__ float g_vt[(size_t)M_*D_];    // [B,H,hd,L]  (transposed!)
__device__ float g_o [(size_t)M_*D_];    // [M,D] attention output
__device__ float g_wt[4][(size_t)D_*D_]; // W^T rounded (q,k,v,o)

// ---------------------------------------------------------------------------
// Baseline-PTX helpers (sm_80-era: valid at target sm_103)
// ---------------------------------------------------------------------------
__device__ __forceinline__ uint32_t smem_to_u32(const void* p) {
    uint32_t a;
    asm("{ .reg .u64 t; cvta.to.shared.u64 t, %1; cvt.u32.u64 %0, t; }"
        : "=r"(a) : "l"(p));
    return a;
}
__device__ __forceinline__ void ldsm_x4(uint32_t addr, uint32_t* r) {
    asm volatile("ldmatrix.sync.aligned.m8n8.x4.shared.b16 {%0,%1,%2,%3}, [%4];"
                 : "=r"(r[0]), "=r"(r[1]), "=r"(r[2]), "=r"(r[3]) : "r"(addr));
}
__device__ __forceinline__ void mma_tf32(float* c, const uint32_t* a,
                                         const uint32_t b0, const uint32_t b1) {
    asm volatile("mma.sync.aligned.m16n8k8.row.col.f32.tf32.tf32.f32 "
                 "{%0,%1,%2,%3}, {%4,%5,%6,%7}, {%8,%9}, {%0,%1,%2,%3};"
                 : "+f"(c[0]), "+f"(c[1]), "+f"(c[2]), "+f"(c[3])
                 : "r"(a[0]), "r"(a[1]), "r"(a[2]), "r"(a[3]), "r"(b0), "r"(b1));
}
__device__ __forceinline__ float rna(float x) {
    uint32_t u;
    asm("cvt.rna.tf32.f32 %0, %1;" : "=r"(u) : "f"(x));
    return __uint_as_float(u);
}
__device__ __forceinline__ uint32_t rna_u(uint32_t x) {
    uint32_t u;
    float f = __uint_as_float(x);
    asm("cvt.rna.tf32.f32 %0, %1;" : "=r"(u) : "f"(f));
    return u;
}
__device__ __forceinline__ float trunc_tf32(float x) {
    return __uint_as_float(__float_as_uint(x) & 0xFFFFE000u);
}
#define CP_ASYNC16(saddr, gptr) \
    asm volatile("cp.async.cg.shared.global [%0], [%1], 16;" \
                 :: "r"(saddr), "l"(gptr))
#define CP_COMMIT()  asm volatile("cp.async.commit_group;" ::: "memory")
#define CP_WAIT(N)   asm volatile("cp.async.wait_group %0;" :: "n"(N) : "memory")

// 256B-row swizzle: XOR 16B-chunk bits [4:7) with row bits [0:3)
#define SW256(row, cb) ((uint32_t)((row) * 256 + ((cb) ^ (((row) & 7) << 4))))

// ---------------------------------------------------------------------------
// Preprocessing: transpose + tf32-round weights (x handled inside qkv_gemm)
// ---------------------------------------------------------------------------
__global__ __launch_bounds__(256)
void pre_w(const float* __restrict__ W0, const float* __restrict__ W1,
           const float* __restrict__ W2, const float* __restrict__ W3,
           float* __restrict__ wt)
{
    __shared__ float t[32][33];
    const int w = blockIdx.z;
    const float* W = (w == 0) ? W0 : (w == 1) ? W1 : (w == 2) ? W2 : W3;
    float* WT = wt + (size_t)w * D_ * D_;
    const int tx = threadIdx.x & 31, ty = threadIdx.x >> 5;   // 32 x 8
    const int x0 = blockIdx.x * 32, y0 = blockIdx.y * 32;
#pragma unroll
    for (int i = 0; i < 32; i += 8)
        t[ty + i][tx] = W[(size_t)(y0 + ty + i) * D_ + x0 + tx];
    __syncthreads();
#pragma unroll
    for (int i = 0; i < 32; i += 8)
        WT[(size_t)(x0 + ty + i) * D_ + y0 + tx] = rna(t[tx][ty + i]);
}

// ---------------------------------------------------------------------------
// tf32 GEMM, WIDE tile: 256x128 CTA, 8 warps (2m x 4n), warp 128x32.
// K-chunks of 64 floats (256B rows), 2-stage cp.async (96KB/stage).
// Per ks: 10 ldsm feed 32 MMAs (-17% ldsm/mma vs 128-tile) and 128
// independent accumulators per warp for deep MMA ILP.
// RNA_A: apply cvt.rna.tf32 to A-fragments after ldmatrix (lets A be raw x).
// ---------------------------------------------------------------------------
#define G2_STAGE 98304
#define G2_OFF_B 65536
#define G2_DYN   (2 * G2_STAGE + 1024)

template<bool RNA_A, typename EpilogueFn>
__device__ __forceinline__
void gemm_core256(const float* __restrict__ A, const float* __restrict__ Bt,
                  int m0, int n0, uint32_t base, EpilogueFn epi)
{
    const int tid  = threadIdx.x;
    const int wid  = tid >> 5;
    const int lane = tid & 31;
    const int wm   = wid & 1;
    const int wn   = wid >> 1;

    // loaders: A row = tid (256 rows x 256B, 16 chunks);
    //          B row = tid>>1, half-row (tid&1)*128B, 8 chunks
    const float* gA = A + (size_t)(m0 + tid) * D_;
    const int blrow = tid >> 1;
    const int blcb0 = (tid & 1) * 128;
    const float* gB = Bt + (size_t)(n0 + blrow) * D_ + (blcb0 >> 2);

    const int arow = wm * 128 + (lane & 7) + ((lane >> 3) & 1) * 8;  // + mi*16
    const int acb  = (lane >> 4) * 16;                               // + ks*32
    const int brow = wn * 32 + (lane & 7) + ((lane >> 4) & 1) * 8;
    const int bcb  = ((lane >> 3) & 1) * 16;

    float acc[8][4][4];
#pragma unroll
    for (int mi = 0; mi < 8; mi++)
#pragma unroll
        for (int nt = 0; nt < 4; nt++)
#pragma unroll
            for (int c = 0; c < 4; c++) acc[mi][nt][c] = 0.0f;

    const int NCHUNK = D_ / 64;   // 12

    // chunk 0 -> stage 0
    {
#pragma unroll
        for (int c = 0; c < 16; c++)
            CP_ASYNC16(base + SW256(tid, c * 16), gA + c * 4);
#pragma unroll
        for (int c = 0; c < 8; c++)
            CP_ASYNC16(base + G2_OFF_B + SW256(blrow, blcb0 + c * 16), gB + c * 4);
    }
    CP_COMMIT();

    for (int i = 0; i < NCHUNK; i++) {
        if (i + 1 < NCHUNK) {
            const uint32_t sb = base + (uint32_t)((i + 1) & 1) * G2_STAGE;
            const int kf = (i + 1) * 64;
#pragma unroll
            for (int c = 0; c < 16; c++)
                CP_ASYNC16(sb + SW256(tid, c * 16), gA + kf + c * 4);
#pragma unroll
            for (int c = 0; c < 8; c++)
                CP_ASYNC16(sb + G2_OFF_B + SW256(blrow, blcb0 + c * 16), gB + kf + c * 4);
            CP_COMMIT();
            CP_WAIT(1);
        } else {
            CP_WAIT(0);
        }
        __syncthreads();

        const uint32_t sb = base + (uint32_t)(i & 1) * G2_STAGE;
#pragma unroll
        for (int ks = 0; ks < 8; ks++) {
            uint32_t a[8][4], bf[2][4];
#pragma unroll
            for (int mi = 0; mi < 8; mi++) {
                ldsm_x4(sb + SW256(arow + mi * 16, acb + ks * 32), a[mi]);
                if (RNA_A) {
#pragma unroll
                    for (int j = 0; j < 4; j++) a[mi][j] = rna_u(a[mi][j]);
                }
            }
#pragma unroll
            for (int nbh = 0; nbh < 2; nbh++)
                ldsm_x4(sb + G2_OFF_B + SW256(brow + nbh * 16, bcb + ks * 32), bf[nbh]);
#pragma unroll
            for (int mi = 0; mi < 8; mi++)
#pragma unroll
                for (int nt = 0; nt < 4; nt++)
                    mma_tf32(acc[mi][nt], a[mi],
                             bf[nt >> 1][(nt & 1) * 2], bf[nt >> 1][(nt & 1) * 2 + 1]);
        }
        __syncthreads();
    }

    const int grp = lane >> 2;
    const int tig = lane & 3;
#pragma unroll
    for (int nt = 0; nt < 4; nt++) {
        const int col = n0 + wn * 32 + nt * 8 + tig * 2;
#pragma unroll
        for (int mi = 0; mi < 8; mi++)
#pragma unroll
            for (int half = 0; half < 2; half++) {
                const int m = m0 + wm * 128 + mi * 16 + grp + half * 8;
                epi(m, col, acc[mi][nt][half * 2 + 0], acc[mi][nt][half * 2 + 1]);
            }
    }
}

// Fused QKV projection: blockIdx.z selects {Wq->q, Wk->k, Wv->vt}.
// A = RAW x; tf32 rounding applied to fragments in-register (RNA_A).
__global__ __launch_bounds__(256)
void qkv_gemm(const float* __restrict__ A, const float* __restrict__ wt,
              const float* __restrict__ bq, const float* __restrict__ bk,
              const float* __restrict__ bv,
              float* __restrict__ Oq, float* __restrict__ Ok,
              float* __restrict__ Ovt)
{
    extern __shared__ char dsm[];
    const uint32_t raw  = smem_to_u32(dsm);
    const uint32_t base = (raw + 1023) & ~1023u;

    const int z = blockIdx.z;
    const float* Bt   = wt + (size_t)z * D_ * D_;
    const float* bias = (z == 0) ? bq : (z == 1) ? bk : bv;
    const float scale = (z == 0) ? 0.125f : 1.0f;
    float* Chl = (z == 0) ? Oq : Ok;

    const int m0 = blockIdx.y * 256;
    const int n0 = blockIdx.x * 128;

    gemm_core256<true>(A, Bt, m0, n0, base,
        [&](int m, int col, float a0, float a1) {
            const float v0 = (a0 + bias[col]) * scale;
            const float v1 = (a1 + bias[col + 1]) * scale;
            const int batch = m / L_, lr = m % L_;
            const int h = col / HD_, d0 = col % HD_;
            if (z < 2) {
                float2 v; v.x = rna(v0); v.y = rna(v1);
                *(float2*)(Chl + (((size_t)(batch * H_ + h) * L_ + lr) * HD_ + d0)) = v;
            } else {
                const size_t vb = ((size_t)(batch * H_ + h) * HD_ + d0) * L_ + lr;
                Ovt[vb]      = rna(v0);
                Ovt[vb + L_] = rna(v1);
            }
        });
}

// Output projection: A = o (already tf32-rounded), fp32 [M,D] out.
__global__ __launch_bounds__(256)
void out_gemm(const float* __restrict__ A, const float* __restrict__ Bt,
              const float* __restrict__ bias, float* __restrict__ C)
{
    extern __shared__ char dsm[];
    const uint32_t raw  = smem_to_u32(dsm);
    const uint32_t base = (raw + 1023) & ~1023u;
    const int m0 = blockIdx.y * 256;
    const int n0 = blockIdx.x * 128;

    gemm_core256<false>(A, Bt, m0, n0, base,
        [&](int m, int col, float a0, float a1) {
            float2 v; v.x = a0 + bias[col]; v.y = a1 + bias[col + 1];
            *(float2*)(C + (size_t)m * D_ + col) = v;
        });
}

// ---------------------------------------------------------------------------
// tf32 flash attention, wide warp tile (32q x 64kv per warp), CTA = 256 q.
// 3-stage cp.async ring -> the prefetch target (it+2)%3 never collides with
// the tile being read, so only ONE __syncthreads per iteration survives.
// P via warp-private smem (tf32-truncated; l summed from same values).
// ---------------------------------------------------------------------------
#define AT_Q    0
#define AT_P    65536
#define AT_STG  131072
#define AT_SSZ  32768
#define AT_VOFF 16384
#define AT_DYN  (AT_STG + 3 * AT_SSZ + 1024)   // 230400 <= 232448

__global__ __launch_bounds__(256)
void attn_tf32(const float* __restrict__ Q, const float* __restrict__ K,
               const float* __restrict__ VT, float* __restrict__ O)
{
    extern __shared__ char dsm[];
    const uint32_t raw  = smem_to_u32(dsm);
    const uint32_t base = (raw + 1023) & ~1023u;
    char* smp = dsm + (base - raw);

    const int tid = threadIdx.x;
    const int wid = tid >> 5;
    const int lane = tid & 31;
    const int b = blockIdx.z, h = blockIdx.y;
    const int q0 = blockIdx.x * 256;
    const size_t hoff = (size_t)(b * H_ + h) * L_ * HD_;

    // Q load: 256 rows x 256B (each thread: 1 row, 16 chunks)
    {
        const float* g = Q + hoff + (size_t)(q0 + tid) * HD_;
#pragma unroll
        for (int c = 0; c < 16; c++)
            CP_ASYNC16(base + AT_Q + SW256(tid, c * 16), g + c * 4);
    }
    const int sr = tid >> 2, scb0 = (tid & 3) * 64;
    auto load_stage = [&](int kt, int stg) {
        const uint32_t sb = base + AT_STG + (uint32_t)stg * AT_SSZ;
        const float* gk = K  + hoff + (size_t)(kt + sr) * HD_ + (scb0 >> 2);
        const float* gv = VT + hoff + (size_t)sr * L_ + kt + (scb0 >> 2);
#pragma unroll
        for (int c = 0; c < 4; c++) {
            const uint32_t so = SW256(sr, scb0 + c * 16);
            CP_ASYNC16(sb + so,           gk + c * 4);
            CP_ASYNC16(sb + AT_VOFF + so, gv + c * 4);
        }
    };
    load_stage(0, 0);  CP_COMMIT();   // group0: Q + stage0
    load_stage(64, 1); CP_COMMIT();   // group1: stage1
    CP_WAIT(1);
    __syncthreads();

    const int ar = (lane & 7) + ((lane >> 3) & 1) * 8;   // A-pattern row
    const int ac = (lane >> 4) * 16;                     // A-pattern col byte
    const int br = (lane & 7) + ((lane >> 4) & 1) * 8;   // B-pattern row
    const int bc = ((lane >> 3) & 1) * 16;               // B-pattern col byte

    float oacc[2][8][4];
#pragma unroll
    for (int qi = 0; qi < 2; qi++)
#pragma unroll
        for (int nt = 0; nt < 8; nt++)
#pragma unroll
            for (int c = 0; c < 4; c++) oacc[qi][nt][c] = 0.0f;
    float lsum[2][2] = {{0.0f, 0.0f}, {0.0f, 0.0f}};

    const uint32_t qrow0 = (uint32_t)(wid * 32);
    const uint32_t pbase = base + AT_P + (uint32_t)wid * 8192;
    char* psmp = smp + AT_P + wid * 8192;
    const int prow = lane >> 2;
    const int pcb  = (lane & 3) * 8;

    const int NIT = L_ / 64;   // 32
    int scomp = 0;             // stage of iteration it (cycles 0,1,2)
    for (int it = 0; it < NIT; it++) {
        const uint32_t sb = base + AT_STG + (uint32_t)scomp * AT_SSZ;

        // ---- S = Q K^T (32 q-rows per warp) ----
        float sacc[2][8][4];
#pragma unroll
        for (int qi = 0; qi < 2; qi++)
#pragma unroll
            for (int nt = 0; nt < 8; nt++)
#pragma unroll
                for (int c = 0; c < 4; c++) sacc[qi][nt][c] = 0.0f;
#pragma unroll
        for (int ks = 0; ks < 8; ks++) {
            uint32_t qa[2][4];
#pragma unroll
            for (int qi = 0; qi < 2; qi++)
                ldsm_x4(base + AT_Q + SW256(qrow0 + qi * 16 + ar, ks * 32 + ac), qa[qi]);
            uint32_t kf[4][4];
#pragma unroll
            for (int nbh = 0; nbh < 4; nbh++)
                ldsm_x4(sb + SW256(nbh * 16 + br, ks * 32 + bc), kf[nbh]);
#pragma unroll
            for (int qi = 0; qi < 2; qi++)
#pragma unroll
                for (int nt = 0; nt < 8; nt++)
                    mma_tf32(sacc[qi][nt], qa[qi],
                             kf[nt >> 1][(nt & 1) * 2], kf[nt >> 1][(nt & 1) * 2 + 1]);
        }

        // ---- P = trunc(exp(S)), partial sums, warp-private smem ----
#pragma unroll
        for (int qi = 0; qi < 2; qi++)
#pragma unroll
            for (int nt = 0; nt < 8; nt++) {
                const float t0 = trunc_tf32(__expf(sacc[qi][nt][0]));
                const float t1 = trunc_tf32(__expf(sacc[qi][nt][1]));
                const float t2 = trunc_tf32(__expf(sacc[qi][nt][2]));
                const float t3 = trunc_tf32(__expf(sacc[qi][nt][3]));
                lsum[qi][0] += t0 + t1;
                lsum[qi][1] += t2 + t3;
                *(float2*)(psmp + SW256(qi * 16 + prow,     nt * 32 + pcb)) =
                    make_float2(t0, t1);
                *(float2*)(psmp + SW256(qi * 16 + prow + 8, nt * 32 + pcb)) =
                    make_float2(t2, t3);
            }
        __syncwarp();

        // ---- O += P V ----
#pragma unroll
        for (int kc = 0; kc < 8; kc++) {
            uint32_t pf[2][4];
#pragma unroll
            for (int qi = 0; qi < 2; qi++)
                ldsm_x4(pbase + SW256(qi * 16 + ar, kc * 32 + ac), pf[qi]);
            uint32_t vf[4][4];
#pragma unroll
            for (int nbh = 0; nbh < 4; nbh++)
                ldsm_x4(sb + AT_VOFF + SW256(nbh * 16 + br, kc * 32 + bc), vf[nbh]);
#pragma unroll
            for (int qi = 0; qi < 2; qi++)
#pragma unroll
                for (int nt = 0; nt < 8; nt++)
                    mma_tf32(oacc[qi][nt], pf[qi],
                             vf[nt >> 1][(nt & 1) * 2], vf[nt >> 1][(nt & 1) * 2 + 1]);
        }

        // ---- pipeline: prefetch it+2 into (it+2)%3 (no collision), then
        //      one wait+sync to guarantee stage it+1 is resident ----
        if (it + 2 < NIT) {
            int snext = scomp + 2; if (snext >= 3) snext -= 3;
            load_stage((it + 2) * 64, snext);
            CP_COMMIT();
        }
        if (it + 1 < NIT) {
            if (it + 2 < NIT) { CP_WAIT(1); } else { CP_WAIT(0); }
            __syncthreads();
        }
        if (++scomp == 3) scomp = 0;
    }

    // ---- epilogue ----
#pragma unroll
    for (int qi = 0; qi < 2; qi++)
#pragma unroll
        for (int hf = 0; hf < 2; hf++) {
            float s = lsum[qi][hf];
            s += __shfl_xor_sync(0xffffffffu, s, 1);
            s += __shfl_xor_sync(0xffffffffu, s, 2);
            lsum[qi][hf] = 1.0f / s;
        }

#pragma unroll
    for (int qi = 0; qi < 2; qi++) {
        const size_t row0 = (size_t)b * L_ + q0 + wid * 32 + qi * 16 + (lane >> 2);
        const size_t row1 = row0 + 8;
        const float inv0 = lsum[qi][0];
        const float inv1 = lsum[qi][1];
#pragma unroll
        for (int nt = 0; nt < 8; nt++) {
            const int col = h * HD_ + nt * 8 + (lane & 3) * 2;
            float2 v0; v0.x = rna(oacc[qi][nt][0] * inv0); v0.y = rna(oacc[qi][nt][1] * inv0);
            float2 v1; v1.x = rna(oacc[qi][nt][2] * inv1); v1.y = rna(oacc[qi][nt][3] * inv1);
            *(float2*)(O + row0 * D_ + col) = v0;
            *(float2*)(O + row1 * D_ + col) = v1;
        }
    }
}

// ---------------------------------------------------------------------------
extern "C" void kernel_launch(void* const* d_in, const int* in_sizes, int n_in,
                              void* d_out, int out_size)
{
    const float* x  = (const float*)d_in[0];
    const float* Wq = (const float*)d_in[1];
    const float* bq = (const float*)d_in[2];
    const float* Wk = (const float*)d_in[3];
    const float* bk = (const float*)d_in[4];
    const float* Wv = (const float*)d_in[5];
    const float* bv = (const float*)d_in[6];
    const float* Wo = (const float*)d_in[7];
    const float* bo = (const float*)d_in[8];
    float* out = (float*)d_out;

    float *q, *k, *vt, *o, *wt;
    cudaGetSymbolAddress((void**)&q,  g_q);
    cudaGetSymbolAddress((void**)&k,  g_k);
    cudaGetSymbolAddress((void**)&vt, g_vt);
    cudaGetSymbolAddress((void**)&o,  g_o);
    cudaGetSymbolAddress((void**)&wt, g_wt);
    const size_t WSZ = (size_t)D_ * D_;

    cudaFuncSetAttribute(qkv_gemm,  cudaFuncAttributeMaxDynamicSharedMemorySize, G2_DYN);
    cudaFuncSetAttribute(out_gemm,  cudaFuncAttributeMaxDynamicSharedMemorySize, G2_DYN);
    cudaFuncSetAttribute(attn_tf32, cudaFuncAttributeMaxDynamicSharedMemorySize, AT_DYN);

    // 1. weight transpose + round (x is rounded in-register inside qkv_gemm)
    pre_w<<<dim3(D_ / 32, D_ / 32, 4), 256>>>(Wq, Wk, Wv, Wo, wt);

    // 2. fused QKV projections (256x128 tiles, 576 CTAs)
    qkv_gemm<<<dim3(D_ / 128, M_ / 256, 3), 256, G2_DYN>>>(
        x, wt, bq, bk, bv, q, k, vt);

    // 3. attention (3-stage ring, one sync/iter)
    attn_tf32<<<dim3(L_ / 256, H_, B_), 256, AT_DYN>>>(q, k, vt, o);

    // 4. output projection
    out_gemm<<<dim3(D_ / 128, M_ / 256), 256, G2_DYN>>>(o, wt + 3 * WSZ, bo, out);
}

// round 13
// speedup vs baseline: 1.6735x; 1.0677x over previous
#include <cuda_runtime.h>
#include <math.h>
#include <stdint.h>

#define B_  4
#define L_  2048
#define D_  768
#define H_  12
#define HD_ 64
#define M_  (B_*L_)

// ---------------------------------------------------------------------------
// Scratch (device globals; all values tf32-rounded fp32)
// K is stored with kv-rows permuted within 8-groups (rho: j<4 -> 2j, else
// 2j-7) so that S-accumulator fragments are directly PV A-fragments.
// ---------------------------------------------------------------------------
__device__ float g_q [(size_t)M_*D_];    // [B,H,L,hd], pre-scaled 1/8
__device__ float g_k [(size_t)M_*D_];    // [B,H,rho(L),hd]  (row-permuted!)
__device__ float g_vt[(size_t)M_*D_];    // [B,H,hd,L]       (transposed)
__device__ float g_o [(size_t)M_*D_];    // [M,D] attention output
__device__ float g_wt[4][(size_t)D_*D_]; // W^T rounded (q,k,v,o)

// ---------------------------------------------------------------------------
// Baseline-PTX helpers (sm_80-era: valid at target sm_103)
// ---------------------------------------------------------------------------
__device__ __forceinline__ uint32_t smem_to_u32(const void* p) {
    uint32_t a;
    asm("{ .reg .u64 t; cvta.to.shared.u64 t, %1; cvt.u32.u64 %0, t; }"
        : "=r"(a) : "l"(p));
    return a;
}
__device__ __forceinline__ void ldsm_x4(uint32_t addr, uint32_t* r) {
    asm volatile("ldmatrix.sync.aligned.m8n8.x4.shared.b16 {%0,%1,%2,%3}, [%4];"
                 : "=r"(r[0]), "=r"(r[1]), "=r"(r[2]), "=r"(r[3]) : "r"(addr));
}
__device__ __forceinline__ void mma_tf32(float* c, const uint32_t* a,
                                         const uint32_t b0, const uint32_t b1) {
    asm volatile("mma.sync.aligned.m16n8k8.row.col.f32.tf32.tf32.f32 "
                 "{%0,%1,%2,%3}, {%4,%5,%6,%7}, {%8,%9}, {%0,%1,%2,%3};"
                 : "+f"(c[0]), "+f"(c[1]), "+f"(c[2]), "+f"(c[3])
                 : "r"(a[0]), "r"(a[1]), "r"(a[2]), "r"(a[3]), "r"(b0), "r"(b1));
}
__device__ __forceinline__ float rna(float x) {
    uint32_t u;
    asm("cvt.rna.tf32.f32 %0, %1;" : "=r"(u) : "f"(x));
    return __uint_as_float(u);
}
__device__ __forceinline__ uint32_t rna_u(uint32_t x) {
    uint32_t u;
    float f = __uint_as_float(x);
    asm("cvt.rna.tf32.f32 %0, %1;" : "=r"(u) : "f"(f));
    return u;
}
__device__ __forceinline__ float trunc_tf32(float x) {
    return __uint_as_float(__float_as_uint(x) & 0xFFFFE000u);
}
#define CP_ASYNC16(saddr, gptr) \
    asm volatile("cp.async.cg.shared.global [%0], [%1], 16;" \
                 :: "r"(saddr), "l"(gptr))
#define CP_COMMIT()  asm volatile("cp.async.commit_group;" ::: "memory")
#define CP_WAIT(N)   asm volatile("cp.async.wait_group %0;" :: "n"(N) : "memory")

// 256B-row swizzle: XOR 16B-chunk bits [4:7) with row bits [0:3)
#define SW256(row, cb) ((uint32_t)((row) * 256 + ((cb) ^ (((row) & 7) << 4))))

// kv permutation within 8-groups: logical l -> physical position
__device__ __forceinline__ int rho_kv(int l) {
    const int j = l & 7;
    return (l & ~7) | ((j < 4) ? (2 * j) : (2 * j - 7));
}

// ---------------------------------------------------------------------------
// Preprocessing: transpose + tf32-round weights
// ---------------------------------------------------------------------------
__global__ __launch_bounds__(256)
void pre_w(const float* __restrict__ W0, const float* __restrict__ W1,
           const float* __restrict__ W2, const float* __restrict__ W3,
           float* __restrict__ wt)
{
    __shared__ float t[32][33];
    const int w = blockIdx.z;
    const float* W = (w == 0) ? W0 : (w == 1) ? W1 : (w == 2) ? W2 : W3;
    float* WT = wt + (size_t)w * D_ * D_;
    const int tx = threadIdx.x & 31, ty = threadIdx.x >> 5;   // 32 x 8
    const int x0 = blockIdx.x * 32, y0 = blockIdx.y * 32;
#pragma unroll
    for (int i = 0; i < 32; i += 8)
        t[ty + i][tx] = W[(size_t)(y0 + ty + i) * D_ + x0 + tx];
    __syncthreads();
#pragma unroll
    for (int i = 0; i < 32; i += 8)
        WT[(size_t)(x0 + ty + i) * D_ + y0 + tx] = rna(t[tx][ty + i]);
}

// ---------------------------------------------------------------------------
// tf32 GEMM core, templated M-tile: MI=8 -> 256x128 CTA (qkv), MI=4 ->
// 128x128 CTA (out; doubles the grid to kill the 1.3-wave tail).
// 8 warps (2m x 4n); K-chunks of 64 floats (256B rows), 2-stage cp.async.
// RNA_A: cvt.rna.tf32 applied to A-fragments post-ldmatrix (A = raw x).
// ---------------------------------------------------------------------------
template<int MI, bool RNA_A, typename EpilogueFn>
__device__ __forceinline__
void gemm_coreT(const float* __restrict__ A, const float* __restrict__ Bt,
                int m0, int n0, uint32_t base, EpilogueFn epi)
{
    constexpr uint32_t OFFB  = (uint32_t)MI * 8192;      // A bytes per stage
    constexpr uint32_t STAGE = OFFB + 32768;             // + B (128x256B)

    const int tid  = threadIdx.x;
    const int wid  = tid >> 5;
    const int lane = tid & 31;
    const int wm   = wid & 1;
    const int wn   = wid >> 1;

    const int blrow = tid >> 1;
    const int blcb0 = (tid & 1) * 128;
    const float* gB = Bt + (size_t)(n0 + blrow) * D_ + (blcb0 >> 2);
    // A loader: MI=8 -> one full 256B row per thread; MI=4 -> half row
    const float* gA = (MI == 8)
        ? A + (size_t)(m0 + tid) * D_
        : A + (size_t)(m0 + blrow) * D_ + (blcb0 >> 2);

    const int arow = wm * (MI * 16) + (lane & 7) + ((lane >> 3) & 1) * 8;
    const int acb  = (lane >> 4) * 16;
    const int brow = wn * 32 + (lane & 7) + ((lane >> 4) & 1) * 8;
    const int bcb  = ((lane >> 3) & 1) * 16;

    float acc[MI][4][4];
#pragma unroll
    for (int mi = 0; mi < MI; mi++)
#pragma unroll
        for (int nt = 0; nt < 4; nt++)
#pragma unroll
            for (int c = 0; c < 4; c++) acc[mi][nt][c] = 0.0f;

    const int NCHUNK = D_ / 64;   // 12

    auto load_chunk = [&](int kc, uint32_t sb) {
        const int kf = kc * 64;
        if (MI == 8) {
#pragma unroll
            for (int c = 0; c < 16; c++)
                CP_ASYNC16(sb + SW256(tid, c * 16), gA + kf + c * 4);
        } else {
#pragma unroll
            for (int c = 0; c < 8; c++)
                CP_ASYNC16(sb + SW256(blrow, blcb0 + c * 16), gA + kf + c * 4);
        }
#pragma unroll
        for (int c = 0; c < 8; c++)
            CP_ASYNC16(sb + OFFB + SW256(blrow, blcb0 + c * 16), gB + kf + c * 4);
    };

    load_chunk(0, base);
    CP_COMMIT();

    for (int i = 0; i < NCHUNK; i++) {
        if (i + 1 < NCHUNK) {
            load_chunk(i + 1, base + (uint32_t)((i + 1) & 1) * STAGE);
            CP_COMMIT();
            CP_WAIT(1);
        } else {
            CP_WAIT(0);
        }
        __syncthreads();

        const uint32_t sb = base + (uint32_t)(i & 1) * STAGE;
#pragma unroll
        for (int ks = 0; ks < 8; ks++) {
            uint32_t a[MI][4], bf[2][4];
#pragma unroll
            for (int mi = 0; mi < MI; mi++) {
                ldsm_x4(sb + SW256(arow + mi * 16, acb + ks * 32), a[mi]);
                if (RNA_A) {
#pragma unroll
                    for (int j = 0; j < 4; j++) a[mi][j] = rna_u(a[mi][j]);
                }
            }
#pragma unroll
            for (int nbh = 0; nbh < 2; nbh++)
                ldsm_x4(sb + OFFB + SW256(brow + nbh * 16, bcb + ks * 32), bf[nbh]);
#pragma unroll
            for (int mi = 0; mi < MI; mi++)
#pragma unroll
                for (int nt = 0; nt < 4; nt++)
                    mma_tf32(acc[mi][nt], a[mi],
                             bf[nt >> 1][(nt & 1) * 2], bf[nt >> 1][(nt & 1) * 2 + 1]);
        }
        __syncthreads();
    }

    const int grp = lane >> 2;
    const int tig = lane & 3;
#pragma unroll
    for (int nt = 0; nt < 4; nt++) {
        const int col = n0 + wn * 32 + nt * 8 + tig * 2;
#pragma unroll
        for (int mi = 0; mi < MI; mi++)
#pragma unroll
            for (int half = 0; half < 2; half++) {
                const int m = m0 + wm * (MI * 16) + mi * 16 + grp + half * 8;
                epi(m, col, acc[mi][nt][half * 2 + 0], acc[mi][nt][half * 2 + 1]);
            }
    }
}

#define GQKV_DYN (2 * (8 * 8192 + 32768) + 1024)   // 197632
#define GOUT_DYN (2 * (4 * 8192 + 32768) + 1024)   // 132096

// Fused QKV projection: blockIdx.z selects {Wq->q, Wk->k (kv-permuted),
// Wv->vt}. A = RAW x; tf32 rounding applied in-register.
__global__ __launch_bounds__(256)
void qkv_gemm(const float* __restrict__ A, const float* __restrict__ wt,
              const float* __restrict__ bq, const float* __restrict__ bk,
              const float* __restrict__ bv,
              float* __restrict__ Oq, float* __restrict__ Ok,
              float* __restrict__ Ovt)
{
    extern __shared__ char dsm[];
    const uint32_t raw  = smem_to_u32(dsm);
    const uint32_t base = (raw + 1023) & ~1023u;

    const int z = blockIdx.z;
    const float* Bt   = wt + (size_t)z * D_ * D_;
    const float* bias = (z == 0) ? bq : (z == 1) ? bk : bv;
    const float scale = (z == 0) ? 0.125f : 1.0f;
    float* Chl = (z == 0) ? Oq : Ok;

    const int m0 = blockIdx.y * 256;
    const int n0 = blockIdx.x * 128;

    gemm_coreT<8, true>(A, Bt, m0, n0, base,
        [&](int m, int col, float a0, float a1) {
            const float v0 = (a0 + bias[col]) * scale;
            const float v1 = (a1 + bias[col + 1]) * scale;
            const int batch = m / L_;
            int lr = m % L_;
            const int h = col / HD_, d0 = col % HD_;
            if (z < 2) {
                if (z == 1) lr = rho_kv(lr);   // K: bake kv permutation
                float2 v; v.x = rna(v0); v.y = rna(v1);
                *(float2*)(Chl + (((size_t)(batch * H_ + h) * L_ + lr) * HD_ + d0)) = v;
            } else {
                const size_t vb = ((size_t)(batch * H_ + h) * HD_ + d0) * L_ + lr;
                Ovt[vb]      = rna(v0);
                Ovt[vb + L_] = rna(v1);
            }
        });
}

// Output projection: 128x128 tiles (grid 384 -> no 1.3-wave tail).
__global__ __launch_bounds__(256)
void out_gemm(const float* __restrict__ A, const float* __restrict__ Bt,
              const float* __restrict__ bias, float* __restrict__ C)
{
    extern __shared__ char dsm[];
    const uint32_t raw  = smem_to_u32(dsm);
    const uint32_t base = (raw + 1023) & ~1023u;
    const int m0 = blockIdx.y * 128;
    const int n0 = blockIdx.x * 128;

    gemm_coreT<4, false>(A, Bt, m0, n0, base,
        [&](int m, int col, float a0, float a1) {
            float2 v; v.x = a0 + bias[col]; v.y = a1 + bias[col + 1];
            *(float2*)(C + (size_t)m * D_ + col) = v;
        });
}

// ---------------------------------------------------------------------------
// tf32 flash attention, wide warp tile (32q x 64kv), CTA = 256 q, 3-stage
// ring, ONE sync/iter. NO P smem round-trip: K is stored kv-permuted so the
// S accumulator fragments (after exp + tf32-truncate, reg order c0,c2,c1,c3)
// ARE the PV A-fragments. V stays in logical order.
// ---------------------------------------------------------------------------
#define AT_Q    0
#define AT_STG  65536
#define AT_SSZ  32768
#define AT_VOFF 16384
#define AT_DYN  (AT_STG + 3 * AT_SSZ + 1024)   // 164864

__global__ __launch_bounds__(256)
void attn_tf32(const float* __restrict__ Q, const float* __restrict__ K,
               const float* __restrict__ VT, float* __restrict__ O)
{
    extern __shared__ char dsm[];
    const uint32_t raw  = smem_to_u32(dsm);
    const uint32_t base = (raw + 1023) & ~1023u;

    const int tid = threadIdx.x;
    const int wid = tid >> 5;
    const int lane = tid & 31;
    const int b = blockIdx.z, h = blockIdx.y;
    const int q0 = blockIdx.x * 256;
    const size_t hoff = (size_t)(b * H_ + h) * L_ * HD_;

    // Q load: 256 rows x 256B (each thread: 1 row, 16 chunks)
    {
        const float* g = Q + hoff + (size_t)(q0 + tid) * HD_;
#pragma unroll
        for (int c = 0; c < 16; c++)
            CP_ASYNC16(base + AT_Q + SW256(tid, c * 16), g + c * 4);
    }
    const int sr = tid >> 2, scb0 = (tid & 3) * 64;
    auto load_stage = [&](int kt, int stg) {
        const uint32_t sb = base + AT_STG + (uint32_t)stg * AT_SSZ;
        const float* gk = K  + hoff + (size_t)(kt + sr) * HD_ + (scb0 >> 2);
        const float* gv = VT + hoff + (size_t)sr * L_ + kt + (scb0 >> 2);
#pragma unroll
        for (int c = 0; c < 4; c++) {
            const uint32_t so = SW256(sr, scb0 + c * 16);
            CP_ASYNC16(sb + so,           gk + c * 4);
            CP_ASYNC16(sb + AT_VOFF + so, gv + c * 4);
        }
    };
    load_stage(0, 0);  CP_COMMIT();   // group0: Q + stage0
    load_stage(64, 1); CP_COMMIT();   // group1: stage1
    CP_WAIT(1);
    __syncthreads();

    const int ar = (lane & 7) + ((lane >> 3) & 1) * 8;   // A-pattern row
    const int ac = (lane >> 4) * 16;                     // A-pattern col byte
    const int br = (lane & 7) + ((lane >> 4) & 1) * 8;   // B-pattern row
    const int bc = ((lane >> 3) & 1) * 16;               // B-pattern col byte

    float oacc[2][8][4];
#pragma unroll
    for (int qi = 0; qi < 2; qi++)
#pragma unroll
        for (int nt = 0; nt < 8; nt++)
#pragma unroll
            for (int c = 0; c < 4; c++) oacc[qi][nt][c] = 0.0f;
    float lsum[2][2] = {{0.0f, 0.0f}, {0.0f, 0.0f}};

    const uint32_t qrow0 = (uint32_t)(wid * 32);

    const int NIT = L_ / 64;   // 32
    int scomp = 0;             // stage of iteration it (cycles 0,1,2)
    for (int it = 0; it < NIT; it++) {
        const uint32_t sb = base + AT_STG + (uint32_t)scomp * AT_SSZ;

        // ---- S = Q K^T (K kv-permuted; columns are "physical") ----
        float sacc[2][8][4];
#pragma unroll
        for (int qi = 0; qi < 2; qi++)
#pragma unroll
            for (int nt = 0; nt < 8; nt++)
#pragma unroll
                for (int c = 0; c < 4; c++) sacc[qi][nt][c] = 0.0f;
#pragma unroll
        for (int ks = 0; ks < 8; ks++) {
            uint32_t qa[2][4];
#pragma unroll
            for (int qi = 0; qi < 2; qi++)
                ldsm_x4(base + AT_Q + SW256(qrow0 + qi * 16 + ar, ks * 32 + ac), qa[qi]);
            uint32_t kf[4][4];
#pragma unroll
            for (int nbh = 0; nbh < 4; nbh++)
                ldsm_x4(sb + SW256(nbh * 16 + br, ks * 32 + bc), kf[nbh]);
#pragma unroll
            for (int qi = 0; qi < 2; qi++)
#pragma unroll
                for (int nt = 0; nt < 8; nt++)
                    mma_tf32(sacc[qi][nt], qa[qi],
                             kf[nt >> 1][(nt & 1) * 2], kf[nt >> 1][(nt & 1) * 2 + 1]);
        }

        // ---- P = trunc(exp(S)) in place + partial row sums ----
#pragma unroll
        for (int qi = 0; qi < 2; qi++)
#pragma unroll
            for (int nt = 0; nt < 8; nt++) {
                sacc[qi][nt][0] = trunc_tf32(__expf(sacc[qi][nt][0]));
                sacc[qi][nt][1] = trunc_tf32(__expf(sacc[qi][nt][1]));
                sacc[qi][nt][2] = trunc_tf32(__expf(sacc[qi][nt][2]));
                sacc[qi][nt][3] = trunc_tf32(__expf(sacc[qi][nt][3]));
                lsum[qi][0] += sacc[qi][nt][0] + sacc[qi][nt][1];
                lsum[qi][1] += sacc[qi][nt][2] + sacc[qi][nt][3];
            }

        // ---- O += P V: S-fragment IS the A-fragment (order c0,c2,c1,c3) ----
#pragma unroll
        for (int kc = 0; kc < 8; kc++) {
            uint32_t vf[4][4];
#pragma unroll
            for (int nbh = 0; nbh < 4; nbh++)
                ldsm_x4(sb + AT_VOFF + SW256(nbh * 16 + br, kc * 32 + bc), vf[nbh]);
#pragma unroll
            for (int qi = 0; qi < 2; qi++) {
                const uint32_t pa[4] = {
                    __float_as_uint(sacc[qi][kc][0]),
                    __float_as_uint(sacc[qi][kc][2]),
                    __float_as_uint(sacc[qi][kc][1]),
                    __float_as_uint(sacc[qi][kc][3]) };
#pragma unroll
                for (int nt = 0; nt < 8; nt++)
                    mma_tf32(oacc[qi][nt], pa,
                             vf[nt >> 1][(nt & 1) * 2], vf[nt >> 1][(nt & 1) * 2 + 1]);
            }
        }

        // ---- pipeline: prefetch it+2 into (it+2)%3, one wait+sync ----
        if (it + 2 < NIT) {
            int snext = scomp + 2; if (snext >= 3) snext -= 3;
            load_stage((it + 2) * 64, snext);
            CP_COMMIT();
        }
        if (it + 1 < NIT) {
            if (it + 2 < NIT) { CP_WAIT(1); } else { CP_WAIT(0); }
            __syncthreads();
        }
        if (++scomp == 3) scomp = 0;
    }

    // ---- epilogue ----
#pragma unroll
    for (int qi = 0; qi < 2; qi++)
#pragma unroll
        for (int hf = 0; hf < 2; hf++) {
            float s = lsum[qi][hf];
            s += __shfl_xor_sync(0xffffffffu, s, 1);
            s += __shfl_xor_sync(0xffffffffu, s, 2);
            lsum[qi][hf] = 1.0f / s;
        }

#pragma unroll
    for (int qi = 0; qi < 2; qi++) {
        const size_t row0 = (size_t)b * L_ + q0 + wid * 32 + qi * 16 + (lane >> 2);
        const size_t row1 = row0 + 8;
        const float inv0 = lsum[qi][0];
        const float inv1 = lsum[qi][1];
#pragma unroll
        for (int nt = 0; nt < 8; nt++) {
            const int col = h * HD_ + nt * 8 + (lane & 3) * 2;
            float2 v0; v0.x = rna(oacc[qi][nt][0] * inv0); v0.y = rna(oacc[qi][nt][1] * inv0);
            float2 v1; v1.x = rna(oacc[qi][nt][2] * inv1); v1.y = rna(oacc[qi][nt][3] * inv1);
            *(float2*)(O + row0 * D_ + col) = v0;
            *(float2*)(O + row1 * D_ + col) = v1;
        }
    }
}

// ---------------------------------------------------------------------------
extern "C" void kernel_launch(void* const* d_in, const int* in_sizes, int n_in,
                              void* d_out, int out_size)
{
    const float* x  = (const float*)d_in[0];
    const float* Wq = (const float*)d_in[1];
    const float* bq = (const float*)d_in[2];
    const float* Wk = (const float*)d_in[3];
    const float* bk = (const float*)d_in[4];
    const float* Wv = (const float*)d_in[5];
    const float* bv = (const float*)d_in[6];
    const float* Wo = (const float*)d_in[7];
    const float* bo = (const float*)d_in[8];
    float* out = (float*)d_out;

    float *q, *k, *vt, *o, *wt;
    cudaGetSymbolAddress((void**)&q,  g_q);
    cudaGetSymbolAddress((void**)&k,  g_k);
    cudaGetSymbolAddress((void**)&vt, g_vt);
    cudaGetSymbolAddress((void**)&o,  g_o);
    cudaGetSymbolAddress((void**)&wt, g_wt);
    const size_t WSZ = (size_t)D_ * D_;

    cudaFuncSetAttribute(qkv_gemm,  cudaFuncAttributeMaxDynamicSharedMemorySize, GQKV_DYN);
    cudaFuncSetAttribute(out_gemm,  cudaFuncAttributeMaxDynamicSharedMemorySize, GOUT_DYN);
    cudaFuncSetAttribute(attn_tf32, cudaFuncAttributeMaxDynamicSharedMemorySize, AT_DYN);

    // 1. weight transpose + round
    pre_w<<<dim3(D_ / 32, D_ / 32, 4), 256>>>(Wq, Wk, Wv, Wo, wt);

    // 2. fused QKV projections (256x128 tiles; K kv-permuted)
    qkv_gemm<<<dim3(D_ / 128, M_ / 256, 3), 256, GQKV_DYN>>>(
        x, wt, bq, bk, bv, q, k, vt);

    // 3. attention (no P round-trip; ncu capture window)
    attn_tf32<<<dim3(L_ / 256, H_, B_), 256, AT_DYN>>>(q, k, vt, o);

    // 4. output projection (128x128 tiles, grid 384)
    out_gemm<<<dim3(D_ / 128, M_ / 128), 256, GOUT_DYN>>>(o, wt + 3 * WSZ, bo, out);
}

// round 14
// speedup vs baseline: 1.8004x; 1.0758x over previous
#include <cuda_runtime.h>
#include <math.h>
#include <stdint.h>

#define B_  4
#define L_  2048
#define D_  768
#define H_  12
#define HD_ 64
#define M_  (B_*L_)

// ---------------------------------------------------------------------------
// Scratch (device globals; all values tf32-rounded fp32)
// K is stored with kv-rows permuted within 8-groups (rho: j<4 -> 2j, else
// 2j-7) so that S-accumulator fragments are directly PV A-fragments.
// ---------------------------------------------------------------------------
__device__ float g_q [(size_t)M_*D_];    // [B,H,L,hd], pre-scaled 1/8
__device__ float g_k [(size_t)M_*D_];    // [B,H,rho(L),hd]  (row-permuted!)
__device__ float g_vt[(size_t)M_*D_];    // [B,H,hd,L]       (transposed)
__device__ float g_o [(size_t)M_*D_];    // [M,D] attention output
__device__ float g_wt[4][(size_t)D_*D_]; // W^T rounded (q,k,v,o)

// ---------------------------------------------------------------------------
// Baseline-PTX helpers (sm_80-era: valid at target sm_103)
// ---------------------------------------------------------------------------
__device__ __forceinline__ uint32_t smem_to_u32(const void* p) {
    uint32_t a;
    asm("{ .reg .u64 t; cvta.to.shared.u64 t, %1; cvt.u32.u64 %0, t; }"
        : "=r"(a) : "l"(p));
    return a;
}
__device__ __forceinline__ void ldsm_x4(uint32_t addr, uint32_t* r) {
    asm volatile("ldmatrix.sync.aligned.m8n8.x4.shared.b16 {%0,%1,%2,%3}, [%4];"
                 : "=r"(r[0]), "=r"(r[1]), "=r"(r[2]), "=r"(r[3]) : "r"(addr));
}
__device__ __forceinline__ void mma_tf32(float* c, const uint32_t* a,
                                         const uint32_t b0, const uint32_t b1) {
    asm volatile("mma.sync.aligned.m16n8k8.row.col.f32.tf32.tf32.f32 "
                 "{%0,%1,%2,%3}, {%4,%5,%6,%7}, {%8,%9}, {%0,%1,%2,%3};"
                 : "+f"(c[0]), "+f"(c[1]), "+f"(c[2]), "+f"(c[3])
                 : "r"(a[0]), "r"(a[1]), "r"(a[2]), "r"(a[3]), "r"(b0), "r"(b1));
}
__device__ __forceinline__ float rna(float x) {
    uint32_t u;
    asm("cvt.rna.tf32.f32 %0, %1;" : "=r"(u) : "f"(x));
    return __uint_as_float(u);
}
__device__ __forceinline__ uint32_t rna_u(uint32_t x) {
    uint32_t u;
    float f = __uint_as_float(x);
    asm("cvt.rna.tf32.f32 %0, %1;" : "=r"(u) : "f"(f));
    return u;
}
__device__ __forceinline__ float trunc_tf32(float x) {
    return __uint_as_float(__float_as_uint(x) & 0xFFFFE000u);
}
#define CP_ASYNC16(saddr, gptr) \
    asm volatile("cp.async.cg.shared.global [%0], [%1], 16;" \
                 :: "r"(saddr), "l"(gptr))
#define CP_COMMIT()  asm volatile("cp.async.commit_group;" ::: "memory")
#define CP_WAIT(N)   asm volatile("cp.async.wait_group %0;" :: "n"(N) : "memory")

// 256B-row swizzle: XOR 16B-chunk bits [4:7) with row bits [0:3)
#define SW256(row, cb) ((uint32_t)((row) * 256 + ((cb) ^ (((row) & 7) << 4))))
// 128B-row swizzle
#define SW128R(row, cb) ((uint32_t)((row) * 128 + ((cb) ^ (((row) & 7) << 4))))

// kv permutation within 8-groups: logical l -> physical position
__device__ __forceinline__ int rho_kv(int l) {
    const int j = l & 7;
    return (l & ~7) | ((j < 4) ? (2 * j) : (2 * j - 7));
}

// ---------------------------------------------------------------------------
// Preprocessing: transpose + tf32-round weights
// ---------------------------------------------------------------------------
__global__ __launch_bounds__(256)
void pre_w(const float* __restrict__ W0, const float* __restrict__ W1,
           const float* __restrict__ W2, const float* __restrict__ W3,
           float* __restrict__ wt)
{
    __shared__ float t[32][33];
    const int w = blockIdx.z;
    const float* W = (w == 0) ? W0 : (w == 1) ? W1 : (w == 2) ? W2 : W3;
    float* WT = wt + (size_t)w * D_ * D_;
    const int tx = threadIdx.x & 31, ty = threadIdx.x >> 5;   // 32 x 8
    const int x0 = blockIdx.x * 32, y0 = blockIdx.y * 32;
#pragma unroll
    for (int i = 0; i < 32; i += 8)
        t[ty + i][tx] = W[(size_t)(y0 + ty + i) * D_ + x0 + tx];
    __syncthreads();
#pragma unroll
    for (int i = 0; i < 32; i += 8)
        WT[(size_t)(x0 + ty + i) * D_ + y0 + tx] = rna(t[tx][ty + i]);
}

// ---------------------------------------------------------------------------
// QKV GEMM: 256x128 CTA tile, 8 warps (2m x 4n), warp 128x32.
// K-chunks of 64 floats (256B rows), 2-stage cp.async (compute/chunk is
// long enough here to hide load latency at 1 CTA/SM).
// A = raw x; cvt.rna.tf32 applied to A-fragments post-ldmatrix.
// ---------------------------------------------------------------------------
#define GQ_OFFB  65536
#define GQ_STAGE (GQ_OFFB + 32768)
#define GQKV_DYN (2 * GQ_STAGE + 1024)

__global__ __launch_bounds__(256)
void qkv_gemm(const float* __restrict__ A, const float* __restrict__ wt,
              const float* __restrict__ bq, const float* __restrict__ bk,
              const float* __restrict__ bv,
              float* __restrict__ Oq, float* __restrict__ Ok,
              float* __restrict__ Ovt)
{
    extern __shared__ char dsm[];
    const uint32_t raw  = smem_to_u32(dsm);
    const uint32_t base = (raw + 1023) & ~1023u;

    const int z = blockIdx.z;
    const float* Bt   = wt + (size_t)z * D_ * D_;
    const float* bias = (z == 0) ? bq : (z == 1) ? bk : bv;
    const float scale = (z == 0) ? 0.125f : 1.0f;
    float* Chl = (z == 0) ? Oq : Ok;

    const int m0 = blockIdx.y * 256;
    const int n0 = blockIdx.x * 128;

    const int tid  = threadIdx.x;
    const int wid  = tid >> 5;
    const int lane = tid & 31;
    const int wm   = wid & 1;
    const int wn   = wid >> 1;

    const int blrow = tid >> 1;
    const int blcb0 = (tid & 1) * 128;
    const float* gA = A  + (size_t)(m0 + tid) * D_;
    const float* gB = Bt + (size_t)(n0 + blrow) * D_ + (blcb0 >> 2);

    const int arow = wm * 128 + (lane & 7) + ((lane >> 3) & 1) * 8;
    const int acb  = (lane >> 4) * 16;
    const int brow = wn * 32 + (lane & 7) + ((lane >> 4) & 1) * 8;
    const int bcb  = ((lane >> 3) & 1) * 16;

    float acc[8][4][4];
#pragma unroll
    for (int mi = 0; mi < 8; mi++)
#pragma unroll
        for (int nt = 0; nt < 4; nt++)
#pragma unroll
            for (int c = 0; c < 4; c++) acc[mi][nt][c] = 0.0f;

    const int NCHUNK = D_ / 64;   // 12
    auto load_chunk = [&](int kc, uint32_t sb) {
        const int kf = kc * 64;
#pragma unroll
        for (int c = 0; c < 16; c++)
            CP_ASYNC16(sb + SW256(tid, c * 16), gA + kf + c * 4);
#pragma unroll
        for (int c = 0; c < 8; c++)
            CP_ASYNC16(sb + GQ_OFFB + SW256(blrow, blcb0 + c * 16), gB + kf + c * 4);
    };

    load_chunk(0, base);
    CP_COMMIT();

    for (int i = 0; i < NCHUNK; i++) {
        if (i + 1 < NCHUNK) {
            load_chunk(i + 1, base + (uint32_t)((i + 1) & 1) * GQ_STAGE);
            CP_COMMIT();
            CP_WAIT(1);
        } else {
            CP_WAIT(0);
        }
        __syncthreads();

        const uint32_t sb = base + (uint32_t)(i & 1) * GQ_STAGE;
#pragma unroll
        for (int ks = 0; ks < 8; ks++) {
            uint32_t a[8][4], bf[2][4];
#pragma unroll
            for (int mi = 0; mi < 8; mi++) {
                ldsm_x4(sb + SW256(arow + mi * 16, acb + ks * 32), a[mi]);
#pragma unroll
                for (int j = 0; j < 4; j++) a[mi][j] = rna_u(a[mi][j]);
            }
#pragma unroll
            for (int nbh = 0; nbh < 2; nbh++)
                ldsm_x4(sb + GQ_OFFB + SW256(brow + nbh * 16, bcb + ks * 32), bf[nbh]);
#pragma unroll
            for (int mi = 0; mi < 8; mi++)
#pragma unroll
                for (int nt = 0; nt < 4; nt++)
                    mma_tf32(acc[mi][nt], a[mi],
                             bf[nt >> 1][(nt & 1) * 2], bf[nt >> 1][(nt & 1) * 2 + 1]);
        }
        __syncthreads();
    }

    const int grp = lane >> 2;
    const int tig = lane & 3;
#pragma unroll
    for (int nt = 0; nt < 4; nt++) {
        const int col = n0 + wn * 32 + nt * 8 + tig * 2;
        const float b0 = bias[col], b1 = bias[col + 1];
#pragma unroll
        for (int mi = 0; mi < 8; mi++)
#pragma unroll
            for (int half = 0; half < 2; half++) {
                const int m = m0 + wm * 128 + mi * 16 + grp + half * 8;
                const float v0 = (acc[mi][nt][half * 2 + 0] + b0) * scale;
                const float v1 = (acc[mi][nt][half * 2 + 1] + b1) * scale;
                const int batch = m / L_;
                int lr = m % L_;
                const int h = col / HD_, d0 = col % HD_;
                if (z < 2) {
                    if (z == 1) lr = rho_kv(lr);   // K: bake kv permutation
                    float2 v; v.x = rna(v0); v.y = rna(v1);
                    *(float2*)(Chl + (((size_t)(batch * H_ + h) * L_ + lr) * HD_ + d0)) = v;
                } else {
                    const size_t vb = ((size_t)(batch * H_ + h) * HD_ + d0) * L_ + lr;
                    Ovt[vb]      = rna(v0);
                    Ovt[vb + L_] = rna(v1);
                }
            }
    }
}

// ---------------------------------------------------------------------------
// Output projection: 128x128 tile, K-chunks of 32 floats (128B rows),
// 3-stage ring with ONE sync per chunk, 2 CTAs/SM (97KB smem, <=128 regs).
// Compute per chunk (~256 cyc/SMSP) << load latency, so residency + deep
// prefetch, not per-CTA pipelining, is what hides the latency here.
// ---------------------------------------------------------------------------
#define GO_OFFB  16384
#define GO_SSZ   32768
#define GOUT_DYN (3 * GO_SSZ + 1024)

__global__ __launch_bounds__(256, 2)
void out_gemm(const float* __restrict__ A, const float* __restrict__ Bt,
              const float* __restrict__ bias, float* __restrict__ C)
{
    extern __shared__ char dsm[];
    const uint32_t raw  = smem_to_u32(dsm);
    const uint32_t base = (raw + 1023) & ~1023u;

    const int m0 = blockIdx.y * 128;
    const int n0 = blockIdx.x * 128;

    const int tid  = threadIdx.x;
    const int wid  = tid >> 5;
    const int lane = tid & 31;
    const int wm   = wid & 1;
    const int wn   = wid >> 1;

    // loader: row tid>>1 (128 rows x 128B), half-row (tid&1)*64B, 4 chunks
    const int lr = tid >> 1;
    const int lc0 = (tid & 1) * 64;
    const float* gA = A  + (size_t)(m0 + lr) * D_ + (lc0 >> 2);
    const float* gB = Bt + (size_t)(n0 + lr) * D_ + (lc0 >> 2);

    const int arow = wm * 64 + (lane & 7) + ((lane >> 3) & 1) * 8;
    const int acb  = (lane >> 4) * 16;
    const int brow = wn * 32 + (lane & 7) + ((lane >> 4) & 1) * 8;
    const int bcb  = ((lane >> 3) & 1) * 16;

    float acc[4][4][4];
#pragma unroll
    for (int mi = 0; mi < 4; mi++)
#pragma unroll
        for (int nt = 0; nt < 4; nt++)
#pragma unroll
            for (int c = 0; c < 4; c++) acc[mi][nt][c] = 0.0f;

    const int NCHUNK = D_ / 32;   // 24
    auto load_chunk = [&](int kc, int stg) {
        const uint32_t sb = base + (uint32_t)stg * GO_SSZ;
        const int kf = kc * 32;
#pragma unroll
        for (int c = 0; c < 4; c++) {
            const uint32_t so = SW128R(lr, lc0 + c * 16);
            CP_ASYNC16(sb + so,           gA + kf + c * 4);
            CP_ASYNC16(sb + GO_OFFB + so, gB + kf + c * 4);
        }
    };

    load_chunk(0, 0); CP_COMMIT();
    load_chunk(1, 1); CP_COMMIT();
    CP_WAIT(1);
    __syncthreads();

    int scomp = 0;
    for (int i = 0; i < NCHUNK; i++) {
        const uint32_t sb = base + (uint32_t)scomp * GO_SSZ;
#pragma unroll
        for (int ks = 0; ks < 4; ks++) {
            uint32_t a[4][4], bf[2][4];
#pragma unroll
            for (int mi = 0; mi < 4; mi++)
                ldsm_x4(sb + SW128R(arow + mi * 16, acb + ks * 32), a[mi]);
#pragma unroll
            for (int nbh = 0; nbh < 2; nbh++)
                ldsm_x4(sb + GO_OFFB + SW128R(brow + nbh * 16, bcb + ks * 32), bf[nbh]);
#pragma unroll
            for (int mi = 0; mi < 4; mi++)
#pragma unroll
                for (int nt = 0; nt < 4; nt++)
                    mma_tf32(acc[mi][nt], a[mi],
                             bf[nt >> 1][(nt & 1) * 2], bf[nt >> 1][(nt & 1) * 2 + 1]);
        }
        // prefetch chunk i+2 into stage (scomp+2)%3; wait for i+1; one sync
        if (i + 2 < NCHUNK) {
            int snext = scomp + 2; if (snext >= 3) snext -= 3;
            load_chunk(i + 2, snext);
            CP_COMMIT();
        }
        if (i + 1 < NCHUNK) {
            if (i + 2 < NCHUNK) { CP_WAIT(1); } else { CP_WAIT(0); }
            __syncthreads();
        }
        if (++scomp == 3) scomp = 0;
    }

    const int grp = lane >> 2;
    const int tig = lane & 3;
#pragma unroll
    for (int nt = 0; nt < 4; nt++) {
        const int col = n0 + wn * 32 + nt * 8 + tig * 2;
        const float b0 = bias[col], b1 = bias[col + 1];
#pragma unroll
        for (int mi = 0; mi < 4; mi++)
#pragma unroll
            for (int half = 0; half < 2; half++) {
                const int m = m0 + wm * 64 + mi * 16 + grp + half * 8;
                float2 v;
                v.x = acc[mi][nt][half * 2 + 0] + b0;
                v.y = acc[mi][nt][half * 2 + 1] + b1;
                *(float2*)(C + (size_t)m * D_ + col) = v;
            }
    }
}

// ---------------------------------------------------------------------------
// tf32 flash attention, wide warp tile (32q x 64kv), CTA = 256 q, 4-stage
// ring (prefetch it+3 -> two tile-load latencies in flight), ONE sync/iter.
// NO P smem round-trip: K stored kv-permuted so S accumulator fragments
// (after exp + tf32-truncate, reg order c0,c2,c1,c3) ARE PV A-fragments.
// ---------------------------------------------------------------------------
#define AT_Q    0
#define AT_STG  65536
#define AT_SSZ  32768
#define AT_VOFF 16384
#define AT_DYN  (AT_STG + 4 * AT_SSZ + 1024)   // 197632

__global__ __launch_bounds__(256)
void attn_tf32(const float* __restrict__ Q, const float* __restrict__ K,
               const float* __restrict__ VT, float* __restrict__ O)
{
    extern __shared__ char dsm[];
    const uint32_t raw  = smem_to_u32(dsm);
    const uint32_t base = (raw + 1023) & ~1023u;

    const int tid = threadIdx.x;
    const int wid = tid >> 5;
    const int lane = tid & 31;
    const int b = blockIdx.z, h = blockIdx.y;
    const int q0 = blockIdx.x * 256;
    const size_t hoff = (size_t)(b * H_ + h) * L_ * HD_;

    // Q load: 256 rows x 256B (each thread: 1 row, 16 chunks)
    {
        const float* g = Q + hoff + (size_t)(q0 + tid) * HD_;
#pragma unroll
        for (int c = 0; c < 16; c++)
            CP_ASYNC16(base + AT_Q + SW256(tid, c * 16), g + c * 4);
    }
    const int sr = tid >> 2, scb0 = (tid & 3) * 64;
    auto load_stage = [&](int kt, int stg) {
        const uint32_t sb = base + AT_STG + (uint32_t)stg * AT_SSZ;
        const float* gk = K  + hoff + (size_t)(kt + sr) * HD_ + (scb0 >> 2);
        const float* gv = VT + hoff + (size_t)sr * L_ + kt + (scb0 >> 2);
#pragma unroll
        for (int c = 0; c < 4; c++) {
            const uint32_t so = SW256(sr, scb0 + c * 16);
            CP_ASYNC16(sb + so,           gk + c * 4);
            CP_ASYNC16(sb + AT_VOFF + so, gv + c * 4);
        }
    };
    load_stage(0, 0);   CP_COMMIT();   // g0: Q + stage0
    load_stage(64, 1);  CP_COMMIT();   // g1: stage1
    load_stage(128, 2); CP_COMMIT();   // g2: stage2
    CP_WAIT(2);                         // Q + stage0 resident
    __syncthreads();

    const int ar = (lane & 7) + ((lane >> 3) & 1) * 8;   // A-pattern row
    const int ac = (lane >> 4) * 16;                     // A-pattern col byte
    const int br = (lane & 7) + ((lane >> 4) & 1) * 8;   // B-pattern row
    const int bc = ((lane >> 3) & 1) * 16;               // B-pattern col byte

    float oacc[2][8][4];
#pragma unroll
    for (int qi = 0; qi < 2; qi++)
#pragma unroll
        for (int nt = 0; nt < 8; nt++)
#pragma unroll
            for (int c = 0; c < 4; c++) oacc[qi][nt][c] = 0.0f;
    float lsum[2][2] = {{0.0f, 0.0f}, {0.0f, 0.0f}};

    const uint32_t qrow0 = (uint32_t)(wid * 32);

    const int NIT = L_ / 64;   // 32
    int scomp = 0;             // stage of iteration it (cycles 0..3)
    for (int it = 0; it < NIT; it++) {
        const uint32_t sb = base + AT_STG + (uint32_t)scomp * AT_SSZ;

        // ---- S = Q K^T (K kv-permuted) ----
        float sacc[2][8][4];
#pragma unroll
        for (int qi = 0; qi < 2; qi++)
#pragma unroll
            for (int nt = 0; nt < 8; nt++)
#pragma unroll
                for (int c = 0; c < 4; c++) sacc[qi][nt][c] = 0.0f;
#pragma unroll
        for (int ks = 0; ks < 8; ks++) {
            uint32_t qa[2][4];
#pragma unroll
            for (int qi = 0; qi < 2; qi++)
                ldsm_x4(base + AT_Q + SW256(qrow0 + qi * 16 + ar, ks * 32 + ac), qa[qi]);
            uint32_t kf[4][4];
#pragma unroll
            for (int nbh = 0; nbh < 4; nbh++)
                ldsm_x4(sb + SW256(nbh * 16 + br, ks * 32 + bc), kf[nbh]);
#pragma unroll
            for (int qi = 0; qi < 2; qi++)
#pragma unroll
                for (int nt = 0; nt < 8; nt++)
                    mma_tf32(sacc[qi][nt], qa[qi],
                             kf[nt >> 1][(nt & 1) * 2], kf[nt >> 1][(nt & 1) * 2 + 1]);
        }

        // ---- P = trunc(exp(S)) in place + partial row sums ----
#pragma unroll
        for (int qi = 0; qi < 2; qi++)
#pragma unroll
            for (int nt = 0; nt < 8; nt++) {
                sacc[qi][nt][0] = trunc_tf32(__expf(sacc[qi][nt][0]));
                sacc[qi][nt][1] = trunc_tf32(__expf(sacc[qi][nt][1]));
                sacc[qi][nt][2] = trunc_tf32(__expf(sacc[qi][nt][2]));
                sacc[qi][nt][3] = trunc_tf32(__expf(sacc[qi][nt][3]));
                lsum[qi][0] += sacc[qi][nt][0] + sacc[qi][nt][1];
                lsum[qi][1] += sacc[qi][nt][2] + sacc[qi][nt][3];
            }

        // ---- O += P V: S-fragment IS the A-fragment (order c0,c2,c1,c3) ----
#pragma unroll
        for (int kc = 0; kc < 8; kc++) {
            uint32_t vf[4][4];
#pragma unroll
            for (int nbh = 0; nbh < 4; nbh++)
                ldsm_x4(sb + AT_VOFF + SW256(nbh * 16 + br, kc * 32 + bc), vf[nbh]);
#pragma unroll
            for (int qi = 0; qi < 2; qi++) {
                const uint32_t pa[4] = {
                    __float_as_uint(sacc[qi][kc][0]),
                    __float_as_uint(sacc[qi][kc][2]),
                    __float_as_uint(sacc[qi][kc][1]),
                    __float_as_uint(sacc[qi][kc][3]) };
#pragma unroll
                for (int nt = 0; nt < 8; nt++)
                    mma_tf32(oacc[qi][nt], pa,
                             vf[nt >> 1][(nt & 1) * 2], vf[nt >> 1][(nt & 1) * 2 + 1]);
            }
        }

        // ---- pipeline: prefetch it+3 into (scomp+3)%4; wait for it+1 ----
        if (it + 3 < NIT) {
            int snext = scomp + 3; if (snext >= 4) snext -= 4;
            load_stage((it + 3) * 64, snext);
            CP_COMMIT();
        }
        if (it + 1 < NIT) {
            if (it + 3 < NIT)      { CP_WAIT(2); }
            else if (it + 2 < NIT) { CP_WAIT(1); }
            else                   { CP_WAIT(0); }
            __syncthreads();
        }
        if (++scomp == 4) scomp = 0;
    }

    // ---- epilogue ----
#pragma unroll
    for (int qi = 0; qi < 2; qi++)
#pragma unroll
        for (int hf = 0; hf < 2; hf++) {
            float s = lsum[qi][hf];
            s += __shfl_xor_sync(0xffffffffu, s, 1);
            s += __shfl_xor_sync(0xffffffffu, s, 2);
            lsum[qi][hf] = 1.0f / s;
        }

#pragma unroll
    for (int qi = 0; qi < 2; qi++) {
        const size_t row0 = (size_t)b * L_ + q0 + wid * 32 + qi * 16 + (lane >> 2);
        const size_t row1 = row0 + 8;
        const float inv0 = lsum[qi][0];
        const float inv1 = lsum[qi][1];
#pragma unroll
        for (int nt = 0; nt < 8; nt++) {
            const int col = h * HD_ + nt * 8 + (lane & 3) * 2;
            float2 v0; v0.x = rna(oacc[qi][nt][0] * inv0); v0.y = rna(oacc[qi][nt][1] * inv0);
            float2 v1; v1.x = rna(oacc[qi][nt][2] * inv1); v1.y = rna(oacc[qi][nt][3] * inv1);
            *(float2*)(O + row0 * D_ + col) = v0;
            *(float2*)(O + row1 * D_ + col) = v1;
        }
    }
}

// ---------------------------------------------------------------------------
extern "C" void kernel_launch(void* const* d_in, const int* in_sizes, int n_in,
                              void* d_out, int out_size)
{
    const float* x  = (const float*)d_in[0];
    const float* Wq = (const float*)d_in[1];
    const float* bq = (const float*)d_in[2];
    const float* Wk = (const float*)d_in[3];
    const float* bk = (const float*)d_in[4];
    const float* Wv = (const float*)d_in[5];
    const float* bv = (const float*)d_in[6];
    const float* Wo = (const float*)d_in[7];
    const float* bo = (const float*)d_in[8];
    float* out = (float*)d_out;

    float *q, *k, *vt, *o, *wt;
    cudaGetSymbolAddress((void**)&q,  g_q);
    cudaGetSymbolAddress((void**)&k,  g_k);
    cudaGetSymbolAddress((void**)&vt, g_vt);
    cudaGetSymbolAddress((void**)&o,  g_o);
    cudaGetSymbolAddress((void**)&wt, g_wt);
    const size_t WSZ = (size_t)D_ * D_;

    cudaFuncSetAttribute(qkv_gemm,  cudaFuncAttributeMaxDynamicSharedMemorySize, GQKV_DYN);
    cudaFuncSetAttribute(out_gemm,  cudaFuncAttributeMaxDynamicSharedMemorySize, GOUT_DYN);
    cudaFuncSetAttribute(attn_tf32, cudaFuncAttributeMaxDynamicSharedMemorySize, AT_DYN);

    // 1. weight transpose + round
    pre_w<<<dim3(D_ / 32, D_ / 32, 4), 256>>>(Wq, Wk, Wv, Wo, wt);

    // 2. fused QKV projections (256x128 tiles; K kv-permuted)
    qkv_gemm<<<dim3(D_ / 128, M_ / 256, 3), 256, GQKV_DYN>>>(
        x, wt, bq, bk, bv, q, k, vt);

    // 3. attention (4-stage ring; ncu capture window)
    attn_tf32<<<dim3(L_ / 256, H_, B_), 256, AT_DYN>>>(q, k, vt, o);

    // 4. output projection (K32, 3-stage, 2 CTAs/SM)
    out_gemm<<<dim3(D_ / 128, M_ / 128), 256, GOUT_DYN>>>(o, wt + 3 * WSZ, bo, out);
}

// round 15
// speedup vs baseline: 2.0729x; 1.1513x over previous
#include <cuda_runtime.h>
#include <math.h>
#include <stdint.h>

#define B_  4
#define L_  2048
#define D_  768
#define H_  12
#define HD_ 64
#define M_  (B_*L_)

// ---------------------------------------------------------------------------
// Scratch (device globals; all values tf32-rounded fp32)
// K is stored with kv-rows permuted within 8-groups (rho: j<4 -> 2j, else
// 2j-7) so that S-accumulator fragments are directly PV A-fragments.
// ---------------------------------------------------------------------------
__device__ float g_q [(size_t)M_*D_];    // [B,H,L,hd], pre-scaled 1/8
__device__ float g_k [(size_t)M_*D_];    // [B,H,rho(L),hd]  (row-permuted!)
__device__ float g_vt[(size_t)M_*D_];    // [B,H,hd,L]       (transposed)
__device__ float g_o [(size_t)M_*D_];    // [M,D] attention output
__device__ float g_wt[4][(size_t)D_*D_]; // W^T rounded (q,k,v,o)

// ---------------------------------------------------------------------------
// Baseline-PTX helpers (sm_80-era: valid at target sm_103)
// ---------------------------------------------------------------------------
__device__ __forceinline__ uint32_t smem_to_u32(const void* p) {
    uint32_t a;
    asm("{ .reg .u64 t; cvta.to.shared.u64 t, %1; cvt.u32.u64 %0, t; }"
        : "=r"(a) : "l"(p));
    return a;
}
__device__ __forceinline__ void ldsm_x4(uint32_t addr, uint32_t* r) {
    asm volatile("ldmatrix.sync.aligned.m8n8.x4.shared.b16 {%0,%1,%2,%3}, [%4];"
                 : "=r"(r[0]), "=r"(r[1]), "=r"(r[2]), "=r"(r[3]) : "r"(addr));
}
__device__ __forceinline__ void mma_tf32(float* c, const uint32_t* a,
                                         const uint32_t b0, const uint32_t b1) {
    asm volatile("mma.sync.aligned.m16n8k8.row.col.f32.tf32.tf32.f32 "
                 "{%0,%1,%2,%3}, {%4,%5,%6,%7}, {%8,%9}, {%0,%1,%2,%3};"
                 : "+f"(c[0]), "+f"(c[1]), "+f"(c[2]), "+f"(c[3])
                 : "r"(a[0]), "r"(a[1]), "r"(a[2]), "r"(a[3]), "r"(b0), "r"(b1));
}
__device__ __forceinline__ float rna(float x) {
    uint32_t u;
    asm("cvt.rna.tf32.f32 %0, %1;" : "=r"(u) : "f"(x));
    return __uint_as_float(u);
}
__device__ __forceinline__ uint32_t rna_u(uint32_t x) {
    uint32_t u;
    float f = __uint_as_float(x);
    asm("cvt.rna.tf32.f32 %0, %1;" : "=r"(u) : "f"(f));
    return u;
}
__device__ __forceinline__ float trunc_tf32(float x) {
    return __uint_as_float(__float_as_uint(x) & 0xFFFFE000u);
}
#define CP_ASYNC16(saddr, gptr) \
    asm volatile("cp.async.cg.shared.global [%0], [%1], 16;" \
                 :: "r"(saddr), "l"(gptr))
#define CP_COMMIT()  asm volatile("cp.async.commit_group;" ::: "memory")
#define CP_WAIT(N)   asm volatile("cp.async.wait_group %0;" :: "n"(N) : "memory")

// 256B-row swizzle: XOR 16B-chunk bits [4:7) with row bits [0:3)
#define SW256(row, cb) ((uint32_t)((row) * 256 + ((cb) ^ (((row) & 7) << 4))))
// 128B-row swizzle
#define SW128R(row, cb) ((uint32_t)((row) * 128 + ((cb) ^ (((row) & 7) << 4))))

// kv permutation within 8-groups: logical l -> physical position
__device__ __forceinline__ int rho_kv(int l) {
    const int j = l & 7;
    return (l & ~7) | ((j < 4) ? (2 * j) : (2 * j - 7));
}

// ---------------------------------------------------------------------------
// Preprocessing: transpose + tf32-round weights
// ---------------------------------------------------------------------------
__global__ __launch_bounds__(256)
void pre_w(const float* __restrict__ W0, const float* __restrict__ W1,
           const float* __restrict__ W2, const float* __restrict__ W3,
           float* __restrict__ wt)
{
    __shared__ float t[32][33];
    const int w = blockIdx.z;
    const float* W = (w == 0) ? W0 : (w == 1) ? W1 : (w == 2) ? W2 : W3;
    float* WT = wt + (size_t)w * D_ * D_;
    const int tx = threadIdx.x & 31, ty = threadIdx.x >> 5;   // 32 x 8
    const int x0 = blockIdx.x * 32, y0 = blockIdx.y * 32;
#pragma unroll
    for (int i = 0; i < 32; i += 8)
        t[ty + i][tx] = W[(size_t)(y0 + ty + i) * D_ + x0 + tx];
    __syncthreads();
#pragma unroll
    for (int i = 0; i < 32; i += 8)
        WT[(size_t)(x0 + ty + i) * D_ + y0 + tx] = rna(t[tx][ty + i]);
}

// ---------------------------------------------------------------------------
// GEMM mainloop (out_gemm-proven config): 128x128 tile, 8 warps (2m x 4n),
// K-chunks of 32 floats (128B rows), 3-stage ring, ONE sync per chunk,
// 2 CTAs/SM (97KB smem, <=128 regs via __launch_bounds__(256,2)).
// RNA_A applies cvt.rna.tf32 to A-fragments post-ldmatrix (A = raw input).
// ---------------------------------------------------------------------------
#define GO_OFFB  16384
#define GO_SSZ   32768
#define G_DYN    (3 * GO_SSZ + 1024)

template<bool RNA_A>
__device__ __forceinline__
void gemm_main128(const float* __restrict__ A, const float* __restrict__ Bt,
                  int m0, int n0, uint32_t base, float acc[4][4][4])
{
    const int tid  = threadIdx.x;
    const int wid  = tid >> 5;
    const int lane = tid & 31;
    const int wm   = wid & 1;
    const int wn   = wid >> 1;

    const int lr = tid >> 1;
    const int lc0 = (tid & 1) * 64;
    const float* gA = A  + (size_t)(m0 + lr) * D_ + (lc0 >> 2);
    const float* gB = Bt + (size_t)(n0 + lr) * D_ + (lc0 >> 2);

    const int arow = wm * 64 + (lane & 7) + ((lane >> 3) & 1) * 8;
    const int acb  = (lane >> 4) * 16;
    const int brow = wn * 32 + (lane & 7) + ((lane >> 4) & 1) * 8;
    const int bcb  = ((lane >> 3) & 1) * 16;

#pragma unroll
    for (int mi = 0; mi < 4; mi++)
#pragma unroll
        for (int nt = 0; nt < 4; nt++)
#pragma unroll
            for (int c = 0; c < 4; c++) acc[mi][nt][c] = 0.0f;

    const int NCHUNK = D_ / 32;   // 24
    auto load_chunk = [&](int kc, int stg) {
        const uint32_t sb = base + (uint32_t)stg * GO_SSZ;
        const int kf = kc * 32;
#pragma unroll
        for (int c = 0; c < 4; c++) {
            const uint32_t so = SW128R(lr, lc0 + c * 16);
            CP_ASYNC16(sb + so,           gA + kf + c * 4);
            CP_ASYNC16(sb + GO_OFFB + so, gB + kf + c * 4);
        }
    };

    load_chunk(0, 0); CP_COMMIT();
    load_chunk(1, 1); CP_COMMIT();
    CP_WAIT(1);
    __syncthreads();

    int scomp = 0;
    for (int i = 0; i < NCHUNK; i++) {
        const uint32_t sb = base + (uint32_t)scomp * GO_SSZ;
#pragma unroll
        for (int ks = 0; ks < 4; ks++) {
            uint32_t a[4][4], bf[2][4];
#pragma unroll
            for (int mi = 0; mi < 4; mi++) {
                ldsm_x4(sb + SW128R(arow + mi * 16, acb + ks * 32), a[mi]);
                if (RNA_A) {
#pragma unroll
                    for (int j = 0; j < 4; j++) a[mi][j] = rna_u(a[mi][j]);
                }
            }
#pragma unroll
            for (int nbh = 0; nbh < 2; nbh++)
                ldsm_x4(sb + GO_OFFB + SW128R(brow + nbh * 16, bcb + ks * 32), bf[nbh]);
#pragma unroll
            for (int mi = 0; mi < 4; mi++)
#pragma unroll
                for (int nt = 0; nt < 4; nt++)
                    mma_tf32(acc[mi][nt], a[mi],
                             bf[nt >> 1][(nt & 1) * 2], bf[nt >> 1][(nt & 1) * 2 + 1]);
        }
        if (i + 2 < NCHUNK) {
            int snext = scomp + 2; if (snext >= 3) snext -= 3;
            load_chunk(i + 2, snext);
            CP_COMMIT();
        }
        if (i + 1 < NCHUNK) {
            if (i + 2 < NCHUNK) { CP_WAIT(1); } else { CP_WAIT(0); }
            __syncthreads();
        }
        if (++scomp == 3) scomp = 0;
    }
}

// Fused QKV projection (out_gemm recipe + qkv epilogue).
// blockIdx.z selects {Wq->q, Wk->k (kv-permuted), Wv->vt}. A = raw x.
__global__ __launch_bounds__(256, 2)
void qkv_gemm(const float* __restrict__ A, const float* __restrict__ wt,
              const float* __restrict__ bq, const float* __restrict__ bk,
              const float* __restrict__ bv,
              float* __restrict__ Oq, float* __restrict__ Ok,
              float* __restrict__ Ovt)
{
    extern __shared__ char dsm[];
    const uint32_t raw  = smem_to_u32(dsm);
    const uint32_t base = (raw + 1023) & ~1023u;

    const int z = blockIdx.z;
    const float* Bt   = wt + (size_t)z * D_ * D_;
    const float* bias = (z == 0) ? bq : (z == 1) ? bk : bv;
    const float scale = (z == 0) ? 0.125f : 1.0f;
    float* Chl = (z == 0) ? Oq : Ok;

    const int m0 = blockIdx.y * 128;
    const int n0 = blockIdx.x * 128;

    float acc[4][4][4];
    gemm_main128<true>(A, Bt, m0, n0, base, acc);

    const int lane = threadIdx.x & 31;
    const int wid  = threadIdx.x >> 5;
    const int wm = wid & 1, wn = wid >> 1;
    const int grp = lane >> 2;
    const int tig = lane & 3;
#pragma unroll
    for (int nt = 0; nt < 4; nt++) {
        const int col = n0 + wn * 32 + nt * 8 + tig * 2;
        const float b0 = bias[col], b1 = bias[col + 1];
#pragma unroll
        for (int mi = 0; mi < 4; mi++)
#pragma unroll
            for (int half = 0; half < 2; half++) {
                const int m = m0 + wm * 64 + mi * 16 + grp + half * 8;
                const float v0 = (acc[mi][nt][half * 2 + 0] + b0) * scale;
                const float v1 = (acc[mi][nt][half * 2 + 1] + b1) * scale;
                const int batch = m / L_;
                int lrow = m % L_;
                const int h = col / HD_, d0 = col % HD_;
                if (z < 2) {
                    if (z == 1) lrow = rho_kv(lrow);   // K: bake kv permutation
                    float2 v; v.x = rna(v0); v.y = rna(v1);
                    *(float2*)(Chl + (((size_t)(batch * H_ + h) * L_ + lrow) * HD_ + d0)) = v;
                } else {
                    const size_t vb = ((size_t)(batch * H_ + h) * HD_ + d0) * L_ + lrow;
                    Ovt[vb]      = rna(v0);
                    Ovt[vb + L_] = rna(v1);
                }
            }
    }
}

// Output projection (same mainloop, fp32 [M,D] epilogue).
__global__ __launch_bounds__(256, 2)
void out_gemm(const float* __restrict__ A, const float* __restrict__ Bt,
              const float* __restrict__ bias, float* __restrict__ C)
{
    extern __shared__ char dsm[];
    const uint32_t raw  = smem_to_u32(dsm);
    const uint32_t base = (raw + 1023) & ~1023u;
    const int m0 = blockIdx.y * 128;
    const int n0 = blockIdx.x * 128;

    float acc[4][4][4];
    gemm_main128<false>(A, Bt, m0, n0, base, acc);

    const int lane = threadIdx.x & 31;
    const int wid  = threadIdx.x >> 5;
    const int wm = wid & 1, wn = wid >> 1;
    const int grp = lane >> 2;
    const int tig = lane & 3;
#pragma unroll
    for (int nt = 0; nt < 4; nt++) {
        const int col = n0 + wn * 32 + nt * 8 + tig * 2;
        const float b0 = bias[col], b1 = bias[col + 1];
#pragma unroll
        for (int mi = 0; mi < 4; mi++)
#pragma unroll
            for (int half = 0; half < 2; half++) {
                const int m = m0 + wm * 64 + mi * 16 + grp + half * 8;
                float2 v;
                v.x = acc[mi][nt][half * 2 + 0] + b0;
                v.y = acc[mi][nt][half * 2 + 1] + b1;
                *(float2*)(C + (size_t)m * D_ + col) = v;
            }
    }
}

// ---------------------------------------------------------------------------
// tf32 flash attention, wide warp tile (32q x 64kv), CTA = 256 q, 4-stage
// ring, ONE sync/iter. NO P smem round-trip: K stored kv-permuted so S
// accumulator fragments (after exp + tf32-truncate, order c0,c2,c1,c3)
// ARE PV A-fragments.
// ---------------------------------------------------------------------------
#define AT_Q    0
#define AT_STG  65536
#define AT_SSZ  32768
#define AT_VOFF 16384
#define AT_DYN  (AT_STG + 4 * AT_SSZ + 1024)   // 197632

__global__ __launch_bounds__(256)
void attn_tf32(const float* __restrict__ Q, const float* __restrict__ K,
               const float* __restrict__ VT, float* __restrict__ O)
{
    extern __shared__ char dsm[];
    const uint32_t raw  = smem_to_u32(dsm);
    const uint32_t base = (raw + 1023) & ~1023u;

    const int tid = threadIdx.x;
    const int wid = tid >> 5;
    const int lane = tid & 31;
    const int b = blockIdx.z, h = blockIdx.y;
    const int q0 = blockIdx.x * 256;
    const size_t hoff = (size_t)(b * H_ + h) * L_ * HD_;

    // Q load: 256 rows x 256B (each thread: 1 row, 16 chunks)
    {
        const float* g = Q + hoff + (size_t)(q0 + tid) * HD_;
#pragma unroll
        for (int c = 0; c < 16; c++)
            CP_ASYNC16(base + AT_Q + SW256(tid, c * 16), g + c * 4);
    }
    const int sr = tid >> 2, scb0 = (tid & 3) * 64;
    auto load_stage = [&](int kt, int stg) {
        const uint32_t sb = base + AT_STG + (uint32_t)stg * AT_SSZ;
        const float* gk = K  + hoff + (size_t)(kt + sr) * HD_ + (scb0 >> 2);
        const float* gv = VT + hoff + (size_t)sr * L_ + kt + (scb0 >> 2);
#pragma unroll
        for (int c = 0; c < 4; c++) {
            const uint32_t so = SW256(sr, scb0 + c * 16);
            CP_ASYNC16(sb + so,           gk + c * 4);
            CP_ASYNC16(sb + AT_VOFF + so, gv + c * 4);
        }
    };
    load_stage(0, 0);   CP_COMMIT();   // g0: Q + stage0
    load_stage(64, 1);  CP_COMMIT();   // g1: stage1
    load_stage(128, 2); CP_COMMIT();   // g2: stage2
    CP_WAIT(2);
    __syncthreads();

    const int ar = (lane & 7) + ((lane >> 3) & 1) * 8;
    const int ac = (lane >> 4) * 16;
    const int br = (lane & 7) + ((lane >> 4) & 1) * 8;
    const int bc = ((lane >> 3) & 1) * 16;

    float oacc[2][8][4];
#pragma unroll
    for (int qi = 0; qi < 2; qi++)
#pragma unroll
        for (int nt = 0; nt < 8; nt++)
#pragma unroll
            for (int c = 0; c < 4; c++) oacc[qi][nt][c] = 0.0f;
    float lsum[2][2] = {{0.0f, 0.0f}, {0.0f, 0.0f}};

    const uint32_t qrow0 = (uint32_t)(wid * 32);

    const int NIT = L_ / 64;   // 32
    int scomp = 0;
    for (int it = 0; it < NIT; it++) {
        const uint32_t sb = base + AT_STG + (uint32_t)scomp * AT_SSZ;

        // ---- S = Q K^T (K kv-permuted) ----
        float sacc[2][8][4];
#pragma unroll
        for (int qi = 0; qi < 2; qi++)
#pragma unroll
            for (int nt = 0; nt < 8; nt++)
#pragma unroll
                for (int c = 0; c < 4; c++) sacc[qi][nt][c] = 0.0f;
#pragma unroll
        for (int ks = 0; ks < 8; ks++) {
            uint32_t qa[2][4];
#pragma unroll
            for (int qi = 0; qi < 2; qi++)
                ldsm_x4(base + AT_Q + SW256(qrow0 + qi * 16 + ar, ks * 32 + ac), qa[qi]);
            uint32_t kf[4][4];
#pragma unroll
            for (int nbh = 0; nbh < 4; nbh++)
                ldsm_x4(sb + SW256(nbh * 16 + br, ks * 32 + bc), kf[nbh]);
#pragma unroll
            for (int qi = 0; qi < 2; qi++)
#pragma unroll
                for (int nt = 0; nt < 8; nt++)
                    mma_tf32(sacc[qi][nt], qa[qi],
                             kf[nt >> 1][(nt & 1) * 2], kf[nt >> 1][(nt & 1) * 2 + 1]);
        }

        // ---- P = trunc(exp(S)) in place + partial row sums ----
#pragma unroll
        for (int qi = 0; qi < 2; qi++)
#pragma unroll
            for (int nt = 0; nt < 8; nt++) {
                sacc[qi][nt][0] = trunc_tf32(__expf(sacc[qi][nt][0]));
                sacc[qi][nt][1] = trunc_tf32(__expf(sacc[qi][nt][1]));
                sacc[qi][nt][2] = trunc_tf32(__expf(sacc[qi][nt][2]));
                sacc[qi][nt][3] = trunc_tf32(__expf(sacc[qi][nt][3]));
                lsum[qi][0] += sacc[qi][nt][0] + sacc[qi][nt][1];
                lsum[qi][1] += sacc[qi][nt][2] + sacc[qi][nt][3];
            }

        // ---- O += P V: S-fragment IS the A-fragment (order c0,c2,c1,c3) ----
#pragma unroll
        for (int kc = 0; kc < 8; kc++) {
            uint32_t vf[4][4];
#pragma unroll
            for (int nbh = 0; nbh < 4; nbh++)
                ldsm_x4(sb + AT_VOFF + SW256(nbh * 16 + br, kc * 32 + bc), vf[nbh]);
#pragma unroll
            for (int qi = 0; qi < 2; qi++) {
                const uint32_t pa[4] = {
                    __float_as_uint(sacc[qi][kc][0]),
                    __float_as_uint(sacc[qi][kc][2]),
                    __float_as_uint(sacc[qi][kc][1]),
                    __float_as_uint(sacc[qi][kc][3]) };
#pragma unroll
                for (int nt = 0; nt < 8; nt++)
                    mma_tf32(oacc[qi][nt], pa,
                             vf[nt >> 1][(nt & 1) * 2], vf[nt >> 1][(nt & 1) * 2 + 1]);
            }
        }

        // ---- pipeline: prefetch it+3 into (scomp+3)%4; wait for it+1 ----
        if (it + 3 < NIT) {
            int snext = scomp + 3; if (snext >= 4) snext -= 4;
            load_stage((it + 3) * 64, snext);
            CP_COMMIT();
        }
        if (it + 1 < NIT) {
            if (it + 3 < NIT)      { CP_WAIT(2); }
            else if (it + 2 < NIT) { CP_WAIT(1); }
            else                   { CP_WAIT(0); }
            __syncthreads();
        }
        if (++scomp == 4) scomp = 0;
    }

    // ---- epilogue ----
#pragma unroll
    for (int qi = 0; qi < 2; qi++)
#pragma unroll
        for (int hf = 0; hf < 2; hf++) {
            float s = lsum[qi][hf];
            s += __shfl_xor_sync(0xffffffffu, s, 1);
            s += __shfl_xor_sync(0xffffffffu, s, 2);
            lsum[qi][hf] = 1.0f / s;
        }

#pragma unroll
    for (int qi = 0; qi < 2; qi++) {
        const size_t row0 = (size_t)b * L_ + q0 + wid * 32 + qi * 16 + (lane >> 2);
        const size_t row1 = row0 + 8;
        const float inv0 = lsum[qi][0];
        const float inv1 = lsum[qi][1];
#pragma unroll
        for (int nt = 0; nt < 8; nt++) {
            const int col = h * HD_ + nt * 8 + (lane & 3) * 2;
            float2 v0; v0.x = rna(oacc[qi][nt][0] * inv0); v0.y = rna(oacc[qi][nt][1] * inv0);
            float2 v1; v1.x = rna(oacc[qi][nt][2] * inv1); v1.y = rna(oacc[qi][nt][3] * inv1);
            *(float2*)(O + row0 * D_ + col) = v0;
            *(float2*)(O + row1 * D_ + col) = v1;
        }
    }
}

// ---------------------------------------------------------------------------
extern "C" void kernel_launch(void* const* d_in, const int* in_sizes, int n_in,
                              void* d_out, int out_size)
{
    const float* x  = (const float*)d_in[0];
    const float* Wq = (const float*)d_in[1];
    const float* bq = (const float*)d_in[2];
    const float* Wk = (const float*)d_in[3];
    const float* bk = (const float*)d_in[4];
    const float* Wv = (const float*)d_in[5];
    const float* bv = (const float*)d_in[6];
    const float* Wo = (const float*)d_in[7];
    const float* bo = (const float*)d_in[8];
    float* out = (float*)d_out;

    float *q, *k, *vt, *o, *wt;
    cudaGetSymbolAddress((void**)&q,  g_q);
    cudaGetSymbolAddress((void**)&k,  g_k);
    cudaGetSymbolAddress((void**)&vt, g_vt);
    cudaGetSymbolAddress((void**)&o,  g_o);
    cudaGetSymbolAddress((void**)&wt, g_wt);
    const size_t WSZ = (size_t)D_ * D_;

    cudaFuncSetAttribute(qkv_gemm,  cudaFuncAttributeMaxDynamicSharedMemorySize, G_DYN);
    cudaFuncSetAttribute(out_gemm,  cudaFuncAttributeMaxDynamicSharedMemorySize, G_DYN);
    cudaFuncSetAttribute(attn_tf32, cudaFuncAttributeMaxDynamicSharedMemorySize, AT_DYN);

    // 1. weight transpose + round
    pre_w<<<dim3(D_ / 32, D_ / 32, 4), 256>>>(Wq, Wk, Wv, Wo, wt);

    // 2. fused QKV projections (128x128 tiles, K32, 3-stage, 2 CTAs/SM)
    qkv_gemm<<<dim3(D_ / 128, M_ / 128, 3), 256, G_DYN>>>(
        x, wt, bq, bk, bv, q, k, vt);

    // 3. attention (4-stage ring)
    attn_tf32<<<dim3(L_ / 256, H_, B_), 256, AT_DYN>>>(q, k, vt, o);

    // 4. output projection (K32, 3-stage, 2 CTAs/SM)
    out_gemm<<<dim3(D_ / 128, M_ / 128), 256, G_DYN>>>(o, wt + 3 * WSZ, bo, out);
}